// round 13
// baseline (speedup 1.0000x reference)
#include <cuda_runtime.h>
#include <cuda_fp16.h>
#include <math.h>
#include <stdint.h>

// ---------------------------------------------------------------------------
// HypRelEncoder — round 13 (fp16 node/rel tables):
//  * x table stored fp16 (xh_a/xh_b ping-pong, 80 MB each; fits L2 for k_agg)
//  * layer-1 FUSE writes fp16 x directly (fp32 x1 buffer deleted)
//  * rel table fp16 for QUAL/k_agg
//  * everything else identical to passing round-12 kernel
// ---------------------------------------------------------------------------

#define NE    200000
#define DIM   200
#define D4    50          // DIM / 4
#define NEDGE 500000
#define NQ    400000
#define QROW  (2*NQ)      // 800000
#define NR    200
#define NB    4096
#define QP    6
#define ALPHA 0.8f
#define MSZ   (208*208)   // padded fp16 weight matrix size

#define OFF_SUB 0
#define OFF_REL (NB*DIM)
#define OFF_QO  (2*NB*DIM)
#define OFF_QR  (OFF_QO + NB*QP*DIM)
#define OFF_X   (OFF_QR + NB*QP*DIM)
#define OFF_R   (OFF_X + NE*DIM)

// ---------------- device scratch -------------------------------------------
__device__ __align__(16) __half g_qproj[(size_t)QROW * DIM];  // 320 MB, fp16, CSR order
__device__ __align__(16) __half g_ninh [(size_t)NE * DIM];    // 80 MB fp16
__device__ __align__(16) __half g_nouth[(size_t)NE * DIM];    // 80 MB fp16
__device__ __align__(16) __half g_xha  [(size_t)NE * DIM];    // 80 MB fp16 x (layer in)
__device__ __align__(16) __half g_xhb  [(size_t)NE * DIM];    // 80 MB fp16 x (layer out)
__device__ __align__(16) __half g_rh   [NR * DIM];            // fp16 rel table
__device__ float g_r1[NR * DIM];
__device__ float g_dinv[2 * NE];
__device__ __align__(16) __half g_wh[(size_t)10 * MSZ];       // padded fp16 weights
__device__ int   gi_ecnt[2 * NE];
__device__ int   gi_estart[2 * NE];
__device__ int   gi_ecur[2 * NE];
__device__ int   gi_qcnt[2 * NEDGE];
__device__ int   gi_qstart[2 * NEDGE];
__device__ int   gi_qcur[2 * NEDGE];
__device__ int   gi_qpos[2 * NQ];
__device__ int4  gi_erec[2 * NEDGE];             // (src, ty, qstart, qcnt) sorted
__device__ float g_enm [2 * NEDGE];              // per-edge norm, sorted
__device__ int   gi_part[1024];
__device__ int   gi_psc[1024];

// ---------------- small helpers --------------------------------------------
__global__ void k_zero(float* __restrict__ p, long n) {
    long i = ((long)blockIdx.x * blockDim.x + threadIdx.x) * 4;
    long st = (long)gridDim.x * blockDim.x * 4;
    float4 z = make_float4(0.f, 0.f, 0.f, 0.f);
    for (; i < n; i += st) *(float4*)(p + i) = z;
}
// fp32 -> fp16 vector convert (n multiple of 4)
__global__ void k_convH(const float* __restrict__ in, __half* __restrict__ out, long n) {
    long i = ((long)blockIdx.x * blockDim.x + threadIdx.x) * 4;
    long st = (long)gridDim.x * blockDim.x * 4;
    for (; i < n; i += st) {
        float4 v = *(const float4*)(in + i);
        union { uint2 u; __half2 h[2]; } p;
        p.h[0] = __floats2half2_rn(v.x, v.y);
        p.h[1] = __floats2half2_rn(v.z, v.w);
        *(uint2*)(out + i) = p.u;
    }
}

__global__ void k_count_e(const int* __restrict__ ei, int* __restrict__ cnt) {
    int i = blockIdx.x * blockDim.x + threadIdx.x;
    int st = gridDim.x * blockDim.x;
    for (; i < 2 * NEDGE; i += st)
        atomicAdd(&cnt[((i >= NEDGE) ? NE : 0) + ei[2 * NEDGE + i]], 1);
}
__global__ void k_count_q(const int* __restrict__ qu, int* __restrict__ cnt) {
    int j = blockIdx.x * blockDim.x + threadIdx.x;
    int st = gridDim.x * blockDim.x;
    for (; j < 2 * NQ; j += st)
        atomicAdd(&cnt[((j >= NQ) ? NEDGE : 0) + qu[2 * QROW + j]], 1);
}
__global__ void k_fill_q(const int* __restrict__ qu, int* __restrict__ cur,
                         int* __restrict__ qpos) {
    int j = blockIdx.x * blockDim.x + threadIdx.x;
    int st = gridDim.x * blockDim.x;
    for (; j < 2 * NQ; j += st) {
        int b = ((j >= NQ) ? NEDGE : 0) + qu[2 * QROW + j];
        int pos = atomicAdd(&cur[b], 1);
        qpos[j] = pos;
    }
}
__global__ void k_fill_e(const int* __restrict__ ei, const int* __restrict__ et,
                         const float* __restrict__ dinv,
                         const int* __restrict__ qstart, const int* __restrict__ qcnt,
                         int* __restrict__ cur,
                         int4* __restrict__ erec, float* __restrict__ enm) {
    int i = blockIdx.x * blockDim.x + threadIdx.x;
    int st = gridDim.x * blockDim.x;
    for (; i < 2 * NEDGE; i += st) {
        int d = (i >= NEDGE) ? 1 : 0;
        int e = i - d * NEDGE;
        int src = ei[i];
        int dst = ei[2 * NEDGE + i];
        int pos = atomicAdd(&cur[d * NE + dst], 1);
        int4 r;
        r.x = src;
        r.y = et[i];
        r.z = qstart[d * NEDGE + e];
        r.w = qcnt[d * NEDGE + e];
        erec[pos] = r;
        enm[pos] = dinv[d * NE + src] * dinv[d * NE + dst];
    }
}
__global__ void k_dinv(const int* __restrict__ cnt, float* __restrict__ dinv) {
    int i = blockIdx.x * blockDim.x + threadIdx.x;
    int st = gridDim.x * blockDim.x;
    for (; i < 2 * NE; i += st) {
        int d = (i >= NE) ? 1 : 0;
        int n = i - d * NE;
        int c = cnt[(1 - d) * NE + n];
        dinv[i] = (c > 0) ? rsqrtf((float)c) : 0.f;
    }
}

// W fp32 [200][200] -> fp16 zero-padded [208][208]
__global__ void k_convW(const float* __restrict__ W, __half* __restrict__ dst) {
    int t = blockIdx.x * blockDim.x + threadIdx.x;
    if (t >= MSZ) return;
    int k = t / 208, n = t - k * 208;
    float v = (k < DIM && n < DIM) ? W[k * DIM + n] : 0.f;
    dst[t] = __float2half_rn(v);
}

// ---------------- two-level exclusive scan ----------------------------------
__global__ void k_scan1(const int* __restrict__ in, int* __restrict__ out,
                        int* __restrict__ part, int n) {
    __shared__ int s[1024];
    int t = threadIdx.x;
    int g = blockIdx.x * 1024 + t;
    int v = (g < n) ? in[g] : 0;
    s[t] = v;
    __syncthreads();
    for (int off = 1; off < 1024; off <<= 1) {
        int u = (t >= off) ? s[t - off] : 0;
        __syncthreads();
        s[t] += u;
        __syncthreads();
    }
    if (g < n) out[g] = s[t] - v;
    if (t == 1023 && part) part[blockIdx.x] = s[1023];
}
__global__ void k_scan_add(int* __restrict__ out, const int* __restrict__ psc, int n) {
    int g = blockIdx.x * 1024 + threadIdx.x;
    if (g < n) out[g] += psc[blockIdx.x];
}

// ---------------- fp16 helpers ----------------------------------------------
__device__ __forceinline__ float4 h4f(uint2 u) {
    float2 a = __half22float2(*reinterpret_cast<__half2*>(&u.x));
    float2 b = __half22float2(*reinterpret_cast<__half2*>(&u.y));
    return make_float4(a.x, a.y, b.x, b.y);
}

// ---------------- fp16 tensor-core GEMM --------------------------------------
// C[rows,200] = compose(A)[rows,K] @ W[K,200]; K sections of 200.
// BM=64, 8 warps (4xM, 2xN); full-K A tile; double-buffered reg-staged W.

enum { M_QUAL = 0, M_FUSE = 1, M_PLAIN = 2 };

#define BM  64
#define AST 216       // half stride (432B = 27*16)
#define WST 216

__device__ __forceinline__ uint32_t s2u(const void* p) {
    return (uint32_t)__cvta_generic_to_shared(p);
}
__device__ __forceinline__ void mma16(float* c, uint32_t a0, uint32_t a1,
                                      uint32_t a2, uint32_t a3,
                                      uint32_t b0, uint32_t b1) {
    asm volatile(
        "mma.sync.aligned.m16n8k16.row.col.f32.f16.f16.f32 "
        "{%0,%1,%2,%3},{%4,%5,%6,%7},{%8,%9},{%0,%1,%2,%3};"
        : "+f"(c[0]), "+f"(c[1]), "+f"(c[2]), "+f"(c[3])
        : "r"(a0), "r"(a1), "r"(a2), "r"(a3), "r"(b0), "r"(b1));
}

template <int MODE>
__global__ void __launch_bounds__(256, 2)
k_gemm(const float* __restrict__ A,      // PLAIN: fp32 rows
       const __half* __restrict__ hA,    // FUSE: nin (fp16)
       const __half* __restrict__ hB2,   // FUSE: nout (fp16)
       const __half* __restrict__ hX,    // QUAL: x table | FUSE: loop x source
       const __half* __restrict__ hR,    // QUAL: rel table (fp16)
       const float* __restrict__ relt,   // FUSE: loop_rel (fp32)
       const int* __restrict__ qe, const int* __restrict__ qr,
       const int* __restrict__ opos,     // QUAL: output row permutation
       const __half* __restrict__ Wh,    // fp16 padded; FUSE: 3 consecutive
       float* __restrict__ out,          // FUSE(layer1) / PLAIN output
       __half* __restrict__ hout,        // QUAL qproj | FUSE(layer0) fp16 x-out
       const float* __restrict__ bias,   // FUSE
       int nrows)
{
    __shared__ __align__(16) __half As[BM * AST];
    __shared__ __align__(16) __half Wb[2][16 * WST];
    const int tid = threadIdx.x;
    const int wid = tid >> 5, lane = tid & 31;
    const int wm = wid >> 1, wn = wid & 1;
    const int r4 = lane >> 2, kq = lane & 3;
    const int row0 = blockIdx.x * BM;
    const int NSEC = (MODE == M_FUSE) ? 3 : 1;
    const int k0a = tid / 26, sg0 = tid - k0a * 26;
    const int s1 = tid + 256;
    const int k1a = s1 / 26, sg1 = s1 - k1a * 26;
    const bool h2nd = (tid < 160);

    float acc[13][4];
#pragma unroll
    for (int f = 0; f < 13; f++)
        acc[f][0] = acc[f][1] = acc[f][2] = acc[f][3] = 0.f;

    for (int sec = 0; sec < NSEC; sec++) {
        __syncthreads();   // prev section's MMA reads of As/Wb complete
        // ---- fill full-K A tile (fp16), warp-per-row ----
        for (int rr = wid; rr < BM; rr += 8) {
            int gr = row0 + rr;
            bool valid = gr < nrows;
            if (MODE == M_FUSE && sec < 2) {
                const __half* hrow = (sec == 0 ? hA : hB2) + (size_t)gr * DIM;
#pragma unroll
                for (int h = 0; h < 2; h++) {
                    int k4 = lane + 32 * h;
                    if (k4 >= 54) continue;
                    uint2 v = make_uint2(0, 0);
                    if (valid && k4 < D4)
                        v = ((const uint2*)hrow)[k4];
                    *reinterpret_cast<uint2*>(&As[rr * AST + k4 * 4]) = v;
                }
            } else if (MODE == M_QUAL) {
                const uint2* p1 = valid ? (const uint2*)(hX + (size_t)qe[gr] * DIM) : 0;
                const uint2* p2 = valid ? (const uint2*)(hR + (size_t)qr[gr] * DIM) : 0;
#pragma unroll
                for (int h = 0; h < 2; h++) {
                    int k4 = lane + 32 * h;
                    if (k4 >= 54) continue;
                    uint2 o = make_uint2(0, 0);
                    if (valid && k4 < D4) {
                        float4 xv = h4f(p1[k4]);
                        float4 rv = h4f(p2[k4]);
                        union { uint2 u; __half2 h2[2]; } pk;
                        pk.h2[0] = __floats2half2_rn(xv.x * rv.x, xv.y * rv.y);
                        pk.h2[1] = __floats2half2_rn(xv.z * rv.z, xv.w * rv.w);
                        o = pk.u;
                    }
                    *reinterpret_cast<uint2*>(&As[rr * AST + k4 * 4]) = o;
                }
            } else if (MODE == M_FUSE) {   // sec == 2: loop section (fp16 x)
                const uint2* p1 = valid ? (const uint2*)(hX + (size_t)gr * DIM) : 0;
#pragma unroll
                for (int h = 0; h < 2; h++) {
                    int k4 = lane + 32 * h;
                    if (k4 >= 54) continue;
                    uint2 o = make_uint2(0, 0);
                    if (valid && k4 < D4) {
                        float4 xv = h4f(p1[k4]);
                        float4 lr = ((const float4*)relt)[k4];
                        union { uint2 u; __half2 h2[2]; } pk;
                        pk.h2[0] = __floats2half2_rn(xv.x * lr.x, xv.y * lr.y);
                        pk.h2[1] = __floats2half2_rn(xv.z * lr.z, xv.w * lr.w);
                        o = pk.u;
                    }
                    *reinterpret_cast<uint2*>(&As[rr * AST + k4 * 4]) = o;
                }
            } else {                       // M_PLAIN: fp32 rows
                const float4* p1 = valid ? (const float4*)(A + (size_t)gr * DIM) : 0;
#pragma unroll
                for (int h = 0; h < 2; h++) {
                    int k4 = lane + 32 * h;
                    if (k4 >= 54) continue;
                    float4 v = make_float4(0.f, 0.f, 0.f, 0.f);
                    if (valid && k4 < D4) v = p1[k4];
                    union { uint2 u; __half2 h2[2]; } pk;
                    pk.h2[0] = __floats2half2_rn(v.x, v.y);
                    pk.h2[1] = __floats2half2_rn(v.z, v.w);
                    *reinterpret_cast<uint2*>(&As[rr * AST + k4 * 4]) = pk.u;
                }
            }
        }
        const __half* Wg = Wh + (size_t)sec * MSZ;
        const uint4* Wg4 = (const uint4*)Wg;

        uint4 w0 = Wg4[tid];
        uint4 w1 = h2nd ? Wg4[s1] : make_uint4(0, 0, 0, 0);
        *(uint4*)&Wb[0][k0a * WST + sg0 * 8] = w0;
        if (h2nd) *(uint4*)&Wb[0][k1a * WST + sg1 * 8] = w1;
        w0 = Wg4[416 + tid];
        if (h2nd) w1 = Wg4[416 + s1];
        __syncthreads();        // As + buf0 visible

        for (int ks = 0; ks < 13; ks++) {
            const __half* wb = Wb[ks & 1];
            uint32_t a0, a1, a2, a3;
            uint32_t aaddr = s2u(&As[(wm * 16 + (lane & 15)) * AST
                                     + ks * 16 + ((lane >> 4) << 3)]);
            asm volatile("ldmatrix.sync.aligned.m8n8.x4.shared.b16 {%0,%1,%2,%3}, [%4];"
                         : "=r"(a0), "=r"(a1), "=r"(a2), "=r"(a3) : "r"(aaddr));
            int brow = ((lane >> 3) & 1) * 8 + (lane & 7);
#pragma unroll
            for (int fp = 0; fp < 6; fp++) {
                int n0 = wn * 104 + fp * 16;
                uint32_t b0, b1, b2, b3;
                uint32_t baddr = s2u(&wb[brow * WST + n0 + ((lane >> 4) << 3)]);
                asm volatile("ldmatrix.sync.aligned.m8n8.x4.trans.shared.b16 "
                             "{%0,%1,%2,%3}, [%4];"
                             : "=r"(b0), "=r"(b1), "=r"(b2), "=r"(b3) : "r"(baddr));
                mma16(acc[2 * fp], a0, a1, a2, a3, b0, b1);
                mma16(acc[2 * fp + 1], a0, a1, a2, a3, b2, b3);
            }
            {
                int n0 = wn * 104 + 96;
                uint32_t b0, b1;
                uint32_t baddr = s2u(&wb[brow * WST + n0]);
                asm volatile("ldmatrix.sync.aligned.m8n8.x2.trans.shared.b16 "
                             "{%0,%1}, [%2];"
                             : "=r"(b0), "=r"(b1) : "r"(baddr));
                mma16(acc[12], a0, a1, a2, a3, b0, b1);
            }
            if (ks < 12) {
                __half* db = Wb[(ks + 1) & 1];
                *(uint4*)&db[k0a * WST + sg0 * 8] = w0;
                if (h2nd) *(uint4*)&db[k1a * WST + sg1 * 8] = w1;
                if (ks < 11) {
                    w0 = Wg4[(size_t)(ks + 2) * 416 + tid];
                    if (h2nd) w1 = Wg4[(size_t)(ks + 2) * 416 + s1];
                }
                __syncthreads();
            }
        }
    }

    // ---- epilogue ----
    int gr0 = row0 + wm * 16 + r4;
    int orow[2];
#pragma unroll
    for (int half = 0; half < 2; half++) {
        int gr = gr0 + 8 * half;
        orow[half] = (gr < nrows) ? ((MODE == M_QUAL) ? opos[gr] : gr) : -1;
    }
#pragma unroll
    for (int f = 0; f < 13; f++) {
        int col = wn * 104 + 8 * f + 2 * kq;
        if (col >= DIM) continue;
#pragma unroll
        for (int half = 0; half < 2; half++) {
            if (orow[half] < 0) continue;
            size_t o = (size_t)orow[half] * DIM + col;
            float v0 = acc[f][2 * half], v1 = acc[f][2 * half + 1];
            if (MODE == M_QUAL) {
                *reinterpret_cast<__half2*>(&hout[o]) = __floats2half2_rn(v0, v1);
            } else if (MODE == M_FUSE) {
                float t0 = tanhf(v0 * (1.f / 3.f) + bias[col]);
                float t1 = tanhf(v1 * (1.f / 3.f) + bias[col + 1]);
                if (hout)
                    *reinterpret_cast<__half2*>(&hout[o]) = __floats2half2_rn(t0, t1);
                else {
                    out[o] = t0; out[o + 1] = t1;
                }
            } else {
                out[o] = v0; out[o + 1] = v1;
            }
        }
    }
}

// ---------------- CSR gather aggregation (fp16 tables) -----------------------
__global__ void __launch_bounds__(256)
k_agg(const __half* __restrict__ xh, const __half* __restrict__ rh,
      const int* __restrict__ e_start, const int* __restrict__ e_cnt,
      const int4* __restrict__ erec, const float* __restrict__ enm,
      const __half* __restrict__ qproj,
      __half* __restrict__ ninh, __half* __restrict__ nouth)
{
    int w = (blockIdx.x * blockDim.x + threadIdx.x) >> 5;
    int lane = threadIdx.x & 31;
    if (w >= 2 * NE) return;
    int d = (w >= NE) ? 1 : 0;
    int n = w - d * NE;

    int c0 = lane;
    int c1 = lane + 32;
    bool has1 = (c1 < D4);

    float4 a0 = make_float4(0.f, 0.f, 0.f, 0.f);
    float4 a1 = a0;

    int beg = e_start[w];
    int end = beg + e_cnt[w];
    if (beg < end) {
        int4 rec = erec[beg];
        float nm = enm[beg];
        for (int idx = beg; idx < end; idx++) {
            int4 rec_n = rec;
            float nm_n = nm;
            if (idx + 1 < end) {
                rec_n = erec[idx + 1];
                nm_n = enm[idx + 1];
            }
            if (nm != 0.f) {
                const uint2* xr = (const uint2*)(xh + (size_t)rec.x * DIM);
                const uint2* rr = (const uint2*)(rh + (size_t)rec.y * DIM);
                float4 q0 = make_float4(0.f, 0.f, 0.f, 0.f);
                float4 q1 = q0;
                for (int t = rec.z; t < rec.z + rec.w; t++) {
                    const uint2* qp = (const uint2*)(qproj + (size_t)t * DIM);
                    float4 f = h4f(qp[c0]);
                    q0.x += f.x; q0.y += f.y; q0.z += f.z; q0.w += f.w;
                    if (has1) {
                        float4 g = h4f(qp[c1]);
                        q1.x += g.x; q1.y += g.y; q1.z += g.z; q1.w += g.w;
                    }
                }
                float4 xv = h4f(xr[c0]), rv = h4f(rr[c0]);
                a0.x += nm * xv.x * (ALPHA * rv.x + (1.f - ALPHA) * q0.x);
                a0.y += nm * xv.y * (ALPHA * rv.y + (1.f - ALPHA) * q0.y);
                a0.z += nm * xv.z * (ALPHA * rv.z + (1.f - ALPHA) * q0.z);
                a0.w += nm * xv.w * (ALPHA * rv.w + (1.f - ALPHA) * q0.w);
                if (has1) {
                    float4 xw = h4f(xr[c1]), rw = h4f(rr[c1]);
                    a1.x += nm * xw.x * (ALPHA * rw.x + (1.f - ALPHA) * q1.x);
                    a1.y += nm * xw.y * (ALPHA * rw.y + (1.f - ALPHA) * q1.y);
                    a1.z += nm * xw.z * (ALPHA * rw.z + (1.f - ALPHA) * q1.z);
                    a1.w += nm * xw.w * (ALPHA * rw.w + (1.f - ALPHA) * q1.w);
                }
            }
            rec = rec_n;
            nm = nm_n;
        }
    }
    __half* ob = (d ? nouth : ninh) + (size_t)n * DIM;
    union { uint2 u; __half2 h2[2]; } s0;
    s0.h2[0] = __floats2half2_rn(a0.x, a0.y);
    s0.h2[1] = __floats2half2_rn(a0.z, a0.w);
    ((uint2*)ob)[c0] = s0.u;
    if (has1) {
        union { uint2 u; __half2 h2[2]; } s1;
        s1.h2[0] = __floats2half2_rn(a1.x, a1.y);
        s1.h2[1] = __floats2half2_rn(a1.z, a1.w);
        ((uint2*)ob)[c1] = s1.u;
    }
}

// ---------------- final batched gathers --------------------------------------
__global__ void k_gather(const float* __restrict__ xf, const float* __restrict__ rf,
                         const int* __restrict__ ent_ix, const int* __restrict__ rel_ix,
                         const int* __restrict__ quals_ix, float* __restrict__ out)
{
    int warp = (blockIdx.x * blockDim.x + threadIdx.x) >> 5;
    int lane = threadIdx.x & 31;
    int nwarp = (gridDim.x * blockDim.x) >> 5;
    const int total = NB * 14;
    for (int r = warp; r < total; r += nwarp) {
        int b = r / 14, s = r - b * 14;
        const float* srcp;
        float* dstp;
        if (s == 0)      { srcp = xf + (size_t)ent_ix[b] * DIM;  dstp = out + OFF_SUB + (size_t)b * DIM; }
        else if (s == 1) { srcp = rf + (size_t)rel_ix[b] * DIM;  dstp = out + OFF_REL + (size_t)b * DIM; }
        else if (s < 8)  { int p = s - 2;
                           srcp = xf + (size_t)quals_ix[b * 2 * QP + 2 * p + 1] * DIM;
                           dstp = out + OFF_QO + ((size_t)b * QP + p) * DIM; }
        else             { int p = s - 8;
                           srcp = rf + (size_t)quals_ix[b * 2 * QP + 2 * p] * DIM;
                           dstp = out + OFF_QR + ((size_t)b * QP + p) * DIM; }
        for (int c = lane; c < D4; c += 32)
            ((float4*)dstp)[c] = ((const float4*)srcp)[c];
    }
}

// ---------------------------------------------------------------------------

extern "C" void kernel_launch(void* const* d_in, const int* in_sizes, int n_in,
                              void* d_out, int out_size)
{
    const float* ent        = (const float*)d_in[0];
    const float* rel0       = (const float*)d_in[1];
    const float* w_in[2]    = {(const float*)d_in[2],  (const float*)d_in[7]};
    const float* w_out[2]   = {(const float*)d_in[3],  (const float*)d_in[8]};
    const float* w_loop[2]  = {(const float*)d_in[4],  (const float*)d_in[9]};
    const float* w_rel[2]   = {(const float*)d_in[5],  (const float*)d_in[10]};
    const float* w_q[2]     = {(const float*)d_in[6],  (const float*)d_in[11]};
    const float* loop_rel[2]= {(const float*)d_in[12], (const float*)d_in[13]};
    const float* bias[2]    = {(const float*)d_in[14], (const float*)d_in[15]};
    const int* ei       = (const int*)d_in[16];
    const int* et       = (const int*)d_in[17];
    const int* qu       = (const int*)d_in[18];
    const int* ent_ix   = (const int*)d_in[19];
    const int* rel_ix   = (const int*)d_in[20];
    const int* quals_ix = (const int*)d_in[21];
    float* out = (float*)d_out;

    float *r1, *dinv, *enm;
    __half *qproj, *ninh, *nouth, *xha, *xhb, *rh, *wh;
    int *ecnt, *estart, *ecur, *qcnt, *qstart, *qcur, *qpos, *part, *psc;
    int4* erec;
    cudaGetSymbolAddress((void**)&qproj,  g_qproj);
    cudaGetSymbolAddress((void**)&ninh,   g_ninh);
    cudaGetSymbolAddress((void**)&nouth,  g_nouth);
    cudaGetSymbolAddress((void**)&xha,    g_xha);
    cudaGetSymbolAddress((void**)&xhb,    g_xhb);
    cudaGetSymbolAddress((void**)&rh,     g_rh);
    cudaGetSymbolAddress((void**)&r1,     g_r1);
    cudaGetSymbolAddress((void**)&dinv,   g_dinv);
    cudaGetSymbolAddress((void**)&enm,    g_enm);
    cudaGetSymbolAddress((void**)&wh,     g_wh);
    cudaGetSymbolAddress((void**)&ecnt,   gi_ecnt);
    cudaGetSymbolAddress((void**)&estart, gi_estart);
    cudaGetSymbolAddress((void**)&ecur,   gi_ecur);
    cudaGetSymbolAddress((void**)&qcnt,   gi_qcnt);
    cudaGetSymbolAddress((void**)&qstart, gi_qstart);
    cudaGetSymbolAddress((void**)&qcur,   gi_qcur);
    cudaGetSymbolAddress((void**)&qpos,   gi_qpos);
    cudaGetSymbolAddress((void**)&erec,   gi_erec);
    cudaGetSymbolAddress((void**)&part,   gi_part);
    cudaGetSymbolAddress((void**)&psc,    gi_psc);

    // ---- fp16 weight conversion: per layer {w_in,w_out,w_loop,w_q,w_rel}
    int cb = (MSZ + 255) / 256;
    for (int L = 0; L < 2; L++) {
        k_convW<<<cb, 256>>>(w_in[L],   wh + (size_t)(L * 5 + 0) * MSZ);
        k_convW<<<cb, 256>>>(w_out[L],  wh + (size_t)(L * 5 + 1) * MSZ);
        k_convW<<<cb, 256>>>(w_loop[L], wh + (size_t)(L * 5 + 2) * MSZ);
        k_convW<<<cb, 256>>>(w_q[L],    wh + (size_t)(L * 5 + 3) * MSZ);
        k_convW<<<cb, 256>>>(w_rel[L],  wh + (size_t)(L * 5 + 4) * MSZ);
    }

    // ---- CSR build (records) ----
    k_zero<<<256, 256>>>((float*)ecnt, 2L * NE);
    k_zero<<<512, 256>>>((float*)qcnt, 2L * NEDGE);
    k_count_e<<<2048, 256>>>(ei, ecnt);
    k_count_q<<<2048, 256>>>(qu, qcnt);

    int nbE = (2 * NE + 1023) / 1024;
    k_scan1<<<nbE, 1024>>>(ecnt, estart, part, 2 * NE);
    k_scan1<<<1, 1024>>>(part, psc, (int*)0, nbE);
    k_scan_add<<<nbE, 1024>>>(estart, psc, 2 * NE);

    int nbQ = (2 * NEDGE + 1023) / 1024;
    k_scan1<<<nbQ, 1024>>>(qcnt, qstart, part, 2 * NEDGE);
    k_scan1<<<1, 1024>>>(part, psc, (int*)0, nbQ);
    k_scan_add<<<nbQ, 1024>>>(qstart, psc, 2 * NEDGE);

    k_dinv<<<512, 256>>>(ecnt, dinv);

    cudaMemcpyAsync(qcur, qstart, 2L * NEDGE * sizeof(int), cudaMemcpyDeviceToDevice, 0);
    k_fill_q<<<2048, 256>>>(qu, qcur, qpos);

    cudaMemcpyAsync(ecur, estart, 2L * NE * sizeof(int), cudaMemcpyDeviceToDevice, 0);
    k_fill_e<<<2048, 256>>>(ei, et, dinv, qstart, qcnt, ecur, erec, enm);

    // ---- initial fp16 tables ----
    k_convH<<<4096, 256>>>(ent, xha, (long)NE * DIM);
    k_convH<<<64, 256>>>(rel0, rh, (long)NR * DIM);

    float* xf = out + OFF_X;
    float* rf = out + OFF_R;

    for (int L = 0; L < 2; L++) {
        const __half* xh = L ? xhb : xha;
        const float* rin = L ? (const float*)r1 : rel0;
        float* rout = L ? rf : r1;

        // qproj[qpos[j]] = fp16((x[q_e[j]] ⊙ rel[q_r[j]]) @ w_q)
        k_gemm<M_QUAL><<<(QROW + BM - 1) / BM, 256>>>(
            0, 0, 0, xh, rh, 0, qu + QROW, qu, qpos,
            wh + (size_t)(L * 5 + 3) * MSZ, 0, qproj, 0, QROW);

        // both-direction record-based CSR gather -> ninh / nouth (fp16)
        k_agg<<<(2 * NE * 32 + 255) / 256, 256>>>(
            xh, rh, estart, ecnt, erec, enm, qproj, ninh, nouth);

        // x_out = tanh(([nin|nout|x⊙loop] @ [w_in;w_out;w_loop])/3 + b)
        // layer 0 -> fp16 xhb; layer 1 -> fp32 xf (final output)
        k_gemm<M_FUSE><<<(NE + BM - 1) / BM, 256>>>(
            0, ninh, nouth, xh, 0, loop_rel[L], 0, 0, 0,
            wh + (size_t)(L * 5 + 0) * MSZ,
            L ? xf : 0, L ? (__half*)0 : xhb, bias[L], NE);

        // r_out = r_in @ w_rel (fp32)
        k_gemm<M_PLAIN><<<(NR + BM - 1) / BM, 256>>>(
            rin, 0, 0, 0, 0, 0, 0, 0, 0,
            wh + (size_t)(L * 5 + 4) * MSZ, rout, 0, 0, NR);

        if (L == 0)     // fp16 rel table for layer 1
            k_convH<<<64, 256>>>(r1, rh, (long)NR * DIM);
    }

    k_gather<<<7168, 256>>>(xf, rf, ent_ix, rel_ix, quals_ix, out);
}

// round 14
// speedup vs baseline: 1.0291x; 1.0291x over previous
#include <cuda_runtime.h>
#include <cuda_fp16.h>
#include <math.h>
#include <stdint.h>

// ---------------------------------------------------------------------------
// HypRelEncoder — round 14 (revert r13 fp16-x; entity-sorted QUAL + launch trims):
//  * data layout = round-12 (fp32 x/rel tables, fp16 qproj/nin/nout) [proven 3090us]
//  * QUAL GEMM processes quals in ENTITY-SORTED order (jord) -> ~4x x-row reuse
//  * batched convW (1 launch), fused histograms, fused fills, dual-write scan-add
// ---------------------------------------------------------------------------

#define NE    200000
#define DIM   200
#define D4    50          // DIM / 4
#define NEDGE 500000
#define NQ    400000
#define QROW  (2*NQ)      // 800000
#define NR    200
#define NB    4096
#define QP    6
#define ALPHA 0.8f
#define MSZ   (208*208)   // padded fp16 weight matrix size

#define OFF_SUB 0
#define OFF_REL (NB*DIM)
#define OFF_QO  (2*NB*DIM)
#define OFF_QR  (OFF_QO + NB*QP*DIM)
#define OFF_X   (OFF_QR + NB*QP*DIM)
#define OFF_R   (OFF_X + NE*DIM)

// ---------------- device scratch -------------------------------------------
__device__ __align__(16) __half g_qproj[(size_t)QROW * DIM];  // 320 MB fp16, CSR order
__device__ __align__(16) __half g_ninh [(size_t)NE * DIM];    // 80 MB fp16
__device__ __align__(16) __half g_nouth[(size_t)NE * DIM];    // 80 MB fp16
__device__ float g_x1  [(size_t)NE * DIM];                    // 160 MB fp32 layer-1 x
__device__ float g_r1[NR * DIM];
__device__ float g_dinv[2 * NE];
__device__ __align__(16) __half g_wh[(size_t)10 * MSZ];       // padded fp16 weights
__device__ int   gi_ecnt[2 * NE];
__device__ int   gi_estart[2 * NE];
__device__ int   gi_ecur[2 * NE];
__device__ int   gi_qcnt[2 * NEDGE];
__device__ int   gi_qstart[2 * NEDGE];
__device__ int   gi_qcur[2 * NEDGE];
__device__ int   gi_qpos[2 * NQ];                // qual j -> CSR (qproj) position
__device__ int   gi_qecnt[NE];                   // entity-sort histogram
__device__ int   gi_qecur[NE];                   // entity-sort cursor (scan result)
__device__ int   gi_jord[2 * NQ];                // entity-sorted qual order
__device__ int4  gi_erec[2 * NEDGE];             // (src, ty, qstart, qcnt) sorted
__device__ float g_enm [2 * NEDGE];              // per-edge norm, sorted
__device__ int   gi_part[1024];
__device__ int   gi_psc[1024];

// ---------------- small helpers --------------------------------------------
__global__ void k_zero(float* __restrict__ p, long n) {
    long i = ((long)blockIdx.x * blockDim.x + threadIdx.x) * 4;
    long st = (long)gridDim.x * blockDim.x * 4;
    float4 z = make_float4(0.f, 0.f, 0.f, 0.f);
    for (; i < n; i += st) *(float4*)(p + i) = z;
}

// fused histograms: edge-dst counts, qual-eid counts, qual-entity counts
__global__ void k_counts(const int* __restrict__ ei, const int* __restrict__ qu,
                         int* __restrict__ ecnt, int* __restrict__ qcnt,
                         int* __restrict__ qecnt) {
    int i = blockIdx.x * blockDim.x + threadIdx.x;
    int st = gridDim.x * blockDim.x;
    for (; i < 2 * NEDGE; i += st) {
        atomicAdd(&ecnt[((i >= NEDGE) ? NE : 0) + ei[2 * NEDGE + i]], 1);
        if (i < 2 * NQ) {
            atomicAdd(&qcnt[((i >= NQ) ? NEDGE : 0) + qu[2 * QROW + i]], 1);
            atomicAdd(&qecnt[qu[QROW + i]], 1);
        }
    }
}

// fused fills: qpos (CSR position) + jord (entity-sorted order)
__global__ void k_fill_qj(const int* __restrict__ qu, int* __restrict__ qcur,
                          int* __restrict__ qpos, int* __restrict__ qecur,
                          int* __restrict__ jord) {
    int j = blockIdx.x * blockDim.x + threadIdx.x;
    int st = gridDim.x * blockDim.x;
    for (; j < 2 * NQ; j += st) {
        int b = ((j >= NQ) ? NEDGE : 0) + qu[2 * QROW + j];
        qpos[j] = atomicAdd(&qcur[b], 1);
        int p2 = atomicAdd(&qecur[qu[QROW + j]], 1);
        jord[p2] = j;
    }
}

__global__ void k_fill_e(const int* __restrict__ ei, const int* __restrict__ et,
                         const float* __restrict__ dinv,
                         const int* __restrict__ qstart, const int* __restrict__ qcnt,
                         int* __restrict__ cur,
                         int4* __restrict__ erec, float* __restrict__ enm) {
    int i = blockIdx.x * blockDim.x + threadIdx.x;
    int st = gridDim.x * blockDim.x;
    for (; i < 2 * NEDGE; i += st) {
        int d = (i >= NEDGE) ? 1 : 0;
        int e = i - d * NEDGE;
        int src = ei[i];
        int dst = ei[2 * NEDGE + i];
        int pos = atomicAdd(&cur[d * NE + dst], 1);
        int4 r;
        r.x = src;
        r.y = et[i];
        r.z = qstart[d * NEDGE + e];
        r.w = qcnt[d * NEDGE + e];
        erec[pos] = r;
        enm[pos] = dinv[d * NE + src] * dinv[d * NE + dst];
    }
}
__global__ void k_dinv(const int* __restrict__ cnt, float* __restrict__ dinv) {
    int i = blockIdx.x * blockDim.x + threadIdx.x;
    int st = gridDim.x * blockDim.x;
    for (; i < 2 * NE; i += st) {
        int d = (i >= NE) ? 1 : 0;
        int n = i - d * NE;
        int c = cnt[(1 - d) * NE + n];
        dinv[i] = (c > 0) ? rsqrtf((float)c) : 0.f;
    }
}

// all 10 weight matrices fp32 [200][200] -> fp16 zero-padded [208][208], 1 launch
struct WPtrs { const float* p[10]; };
__global__ void k_convW_all(WPtrs ws, __half* __restrict__ dst) {
    long t = (long)blockIdx.x * blockDim.x + threadIdx.x;
    if (t >= 10L * MSZ) return;
    int m = (int)(t / MSZ);
    int r = (int)(t - (long)m * MSZ);
    int k = r / 208, n = r - k * 208;
    float v = (k < DIM && n < DIM) ? ws.p[m][k * DIM + n] : 0.f;
    dst[t] = __float2half_rn(v);
}

// ---------------- two-level exclusive scan ----------------------------------
__global__ void k_scan1(const int* __restrict__ in, int* __restrict__ out,
                        int* __restrict__ part, int n) {
    __shared__ int s[1024];
    int t = threadIdx.x;
    int g = blockIdx.x * 1024 + t;
    int v = (g < n) ? in[g] : 0;
    s[t] = v;
    __syncthreads();
    for (int off = 1; off < 1024; off <<= 1) {
        int u = (t >= off) ? s[t - off] : 0;
        __syncthreads();
        s[t] += u;
        __syncthreads();
    }
    if (g < n) out[g] = s[t] - v;
    if (t == 1023 && part) part[blockIdx.x] = s[1023];
}
__global__ void k_scan_add(int* __restrict__ out, const int* __restrict__ psc, int n) {
    int g = blockIdx.x * 1024 + threadIdx.x;
    if (g < n) out[g] += psc[blockIdx.x];
}
// adds block offsets AND writes the cursor copy (replaces memcpy)
__global__ void k_scan_add2(int* __restrict__ out, int* __restrict__ cur,
                            const int* __restrict__ psc, int n) {
    int g = blockIdx.x * 1024 + threadIdx.x;
    if (g < n) {
        int v = out[g] + psc[blockIdx.x];
        out[g] = v;
        cur[g] = v;
    }
}

// ---------------- fp16 tensor-core GEMM --------------------------------------
// C[rows,200] = compose(A)[rows,K] @ W[K,200]; K sections of 200.
// BM=64, 8 warps (4xM, 2xN); full-K A tile; double-buffered reg-staged W.

enum { M_QUAL = 0, M_FUSE = 1, M_PLAIN = 2 };

#define BM  64
#define AST 216       // half stride (432B = 27*16)
#define WST 216

__device__ __forceinline__ uint32_t s2u(const void* p) {
    return (uint32_t)__cvta_generic_to_shared(p);
}
__device__ __forceinline__ void mma16(float* c, uint32_t a0, uint32_t a1,
                                      uint32_t a2, uint32_t a3,
                                      uint32_t b0, uint32_t b1) {
    asm volatile(
        "mma.sync.aligned.m16n8k16.row.col.f32.f16.f16.f32 "
        "{%0,%1,%2,%3},{%4,%5,%6,%7},{%8,%9},{%0,%1,%2,%3};"
        : "+f"(c[0]), "+f"(c[1]), "+f"(c[2]), "+f"(c[3])
        : "r"(a0), "r"(a1), "r"(a2), "r"(a3), "r"(b0), "r"(b1));
}

template <int MODE>
__global__ void __launch_bounds__(256, 2)
k_gemm(const float* __restrict__ A,      // QUAL: x table | PLAIN: rows
       const __half* __restrict__ hA,    // FUSE: nin (fp16)
       const __half* __restrict__ hB2,   // FUSE: nout (fp16)
       const float* __restrict__ C3,     // FUSE: x (loop section)
       const float* __restrict__ relt,   // QUAL: rel table | FUSE: loop_rel
       const int* __restrict__ qe, const int* __restrict__ qr,
       const int* __restrict__ jord,     // QUAL: entity-sorted row order
       const int* __restrict__ opos,     // QUAL: output row permutation
       const __half* __restrict__ Wh,    // fp16 padded; FUSE: 3 consecutive
       float* __restrict__ out,          // FUSE / PLAIN output
       __half* __restrict__ hqout,       // QUAL output (fp16)
       const float* __restrict__ bias,   // FUSE
       int nrows)
{
    __shared__ __align__(16) __half As[BM * AST];
    __shared__ __align__(16) __half Wb[2][16 * WST];
    const int tid = threadIdx.x;
    const int wid = tid >> 5, lane = tid & 31;
    const int wm = wid >> 1, wn = wid & 1;
    const int r4 = lane >> 2, kq = lane & 3;
    const int row0 = blockIdx.x * BM;
    const int NSEC = (MODE == M_FUSE) ? 3 : 1;
    const int k0a = tid / 26, sg0 = tid - k0a * 26;
    const int s1 = tid + 256;
    const int k1a = s1 / 26, sg1 = s1 - k1a * 26;
    const bool h2nd = (tid < 160);

    float acc[13][4];
#pragma unroll
    for (int f = 0; f < 13; f++)
        acc[f][0] = acc[f][1] = acc[f][2] = acc[f][3] = 0.f;

    for (int sec = 0; sec < NSEC; sec++) {
        __syncthreads();   // prev section's MMA reads of As/Wb complete
        // ---- fill full-K A tile (fp16), warp-per-row ----
        for (int rr = wid; rr < BM; rr += 8) {
            int gr = row0 + rr;
            bool valid = gr < nrows;
            if (MODE == M_FUSE && sec < 2) {
                const __half* hrow = (sec == 0 ? hA : hB2) + (size_t)gr * DIM;
#pragma unroll
                for (int h = 0; h < 2; h++) {
                    int k4 = lane + 32 * h;
                    if (k4 >= 54) continue;
                    uint2 v = make_uint2(0, 0);
                    if (valid && k4 < D4)
                        v = ((const uint2*)hrow)[k4];
                    *reinterpret_cast<uint2*>(&As[rr * AST + k4 * 4]) = v;
                }
            } else {
                const float4 *p1 = 0, *p2 = 0;
                if (valid) {
                    if (MODE == M_QUAL) {
                        int j = jord[gr];              // entity-sorted order
                        p1 = (const float4*)(A + (size_t)qe[j] * DIM);
                        p2 = (const float4*)(relt + (size_t)qr[j] * DIM);
                    } else if (MODE == M_FUSE) {       // sec == 2: loop section
                        p1 = (const float4*)(C3 + (size_t)gr * DIM);
                        p2 = (const float4*)relt;
                    } else {
                        p1 = (const float4*)(A + (size_t)gr * DIM);
                    }
                }
#pragma unroll
                for (int h = 0; h < 2; h++) {
                    int k4 = lane + 32 * h;
                    if (k4 >= 54) continue;          // 54*4 = 216 = AST
                    float4 v = make_float4(0.f, 0.f, 0.f, 0.f);
                    if (valid && k4 < D4) {
                        v = p1[k4];
                        if (MODE == M_QUAL || MODE == M_FUSE) {
                            float4 r = p2[k4];
                            v.x *= r.x; v.y *= r.y; v.z *= r.z; v.w *= r.w;
                        }
                    }
                    union { uint2 u; __half2 h2[2]; } pk;
                    pk.h2[0] = __floats2half2_rn(v.x, v.y);
                    pk.h2[1] = __floats2half2_rn(v.z, v.w);
                    *reinterpret_cast<uint2*>(&As[rr * AST + k4 * 4]) = pk.u;
                }
            }
        }
        const __half* Wg = Wh + (size_t)sec * MSZ;
        const uint4* Wg4 = (const uint4*)Wg;

        uint4 w0 = Wg4[tid];
        uint4 w1 = h2nd ? Wg4[s1] : make_uint4(0, 0, 0, 0);
        *(uint4*)&Wb[0][k0a * WST + sg0 * 8] = w0;
        if (h2nd) *(uint4*)&Wb[0][k1a * WST + sg1 * 8] = w1;
        w0 = Wg4[416 + tid];
        if (h2nd) w1 = Wg4[416 + s1];
        __syncthreads();        // As + buf0 visible

        for (int ks = 0; ks < 13; ks++) {
            const __half* wb = Wb[ks & 1];
            uint32_t a0, a1, a2, a3;
            uint32_t aaddr = s2u(&As[(wm * 16 + (lane & 15)) * AST
                                     + ks * 16 + ((lane >> 4) << 3)]);
            asm volatile("ldmatrix.sync.aligned.m8n8.x4.shared.b16 {%0,%1,%2,%3}, [%4];"
                         : "=r"(a0), "=r"(a1), "=r"(a2), "=r"(a3) : "r"(aaddr));
            int brow = ((lane >> 3) & 1) * 8 + (lane & 7);
#pragma unroll
            for (int fp = 0; fp < 6; fp++) {
                int n0 = wn * 104 + fp * 16;
                uint32_t b0, b1, b2, b3;
                uint32_t baddr = s2u(&wb[brow * WST + n0 + ((lane >> 4) << 3)]);
                asm volatile("ldmatrix.sync.aligned.m8n8.x4.trans.shared.b16 "
                             "{%0,%1,%2,%3}, [%4];"
                             : "=r"(b0), "=r"(b1), "=r"(b2), "=r"(b3) : "r"(baddr));
                mma16(acc[2 * fp], a0, a1, a2, a3, b0, b1);
                mma16(acc[2 * fp + 1], a0, a1, a2, a3, b2, b3);
            }
            {
                int n0 = wn * 104 + 96;
                uint32_t b0, b1;
                uint32_t baddr = s2u(&wb[brow * WST + n0]);
                asm volatile("ldmatrix.sync.aligned.m8n8.x2.trans.shared.b16 "
                             "{%0,%1}, [%2];"
                             : "=r"(b0), "=r"(b1) : "r"(baddr));
                mma16(acc[12], a0, a1, a2, a3, b0, b1);
            }
            if (ks < 12) {
                __half* db = Wb[(ks + 1) & 1];
                *(uint4*)&db[k0a * WST + sg0 * 8] = w0;
                if (h2nd) *(uint4*)&db[k1a * WST + sg1 * 8] = w1;
                if (ks < 11) {
                    w0 = Wg4[(size_t)(ks + 2) * 416 + tid];
                    if (h2nd) w1 = Wg4[(size_t)(ks + 2) * 416 + s1];
                }
                __syncthreads();
            }
        }
    }

    // ---- epilogue ----
    int gr0 = row0 + wm * 16 + r4;
    int orow[2];
#pragma unroll
    for (int half = 0; half < 2; half++) {
        int gr = gr0 + 8 * half;
        orow[half] = (gr < nrows)
                   ? ((MODE == M_QUAL) ? opos[jord[gr]] : gr) : -1;
    }
#pragma unroll
    for (int f = 0; f < 13; f++) {
        int col = wn * 104 + 8 * f + 2 * kq;
        if (col >= DIM) continue;
#pragma unroll
        for (int half = 0; half < 2; half++) {
            if (orow[half] < 0) continue;
            size_t o = (size_t)orow[half] * DIM + col;
            float v0 = acc[f][2 * half], v1 = acc[f][2 * half + 1];
            if (MODE == M_QUAL) {
                *reinterpret_cast<__half2*>(&hqout[o]) = __floats2half2_rn(v0, v1);
            } else if (MODE == M_FUSE) {
                out[o]     = tanhf(v0 * (1.f / 3.f) + bias[col]);
                out[o + 1] = tanhf(v1 * (1.f / 3.f) + bias[col + 1]);
            } else {
                out[o] = v0; out[o + 1] = v1;
            }
        }
    }
}

// ---------------- CSR gather aggregation (record-based, fp16 qproj/out) ------
__global__ void __launch_bounds__(256)
k_agg(const float* __restrict__ x, const float* __restrict__ relt,
      const int* __restrict__ e_start, const int* __restrict__ e_cnt,
      const int4* __restrict__ erec, const float* __restrict__ enm,
      const __half* __restrict__ qproj,
      __half* __restrict__ ninh, __half* __restrict__ nouth)
{
    int w = (blockIdx.x * blockDim.x + threadIdx.x) >> 5;
    int lane = threadIdx.x & 31;
    if (w >= 2 * NE) return;
    int d = (w >= NE) ? 1 : 0;
    int n = w - d * NE;

    int c0 = lane;
    int c1 = lane + 32;
    bool has1 = (c1 < D4);

    float4 a0 = make_float4(0.f, 0.f, 0.f, 0.f);
    float4 a1 = a0;

    int beg = e_start[w];
    int end = beg + e_cnt[w];
    if (beg < end) {
        int4 rec = erec[beg];
        float nm = enm[beg];
        for (int idx = beg; idx < end; idx++) {
            int4 rec_n = rec;
            float nm_n = nm;
            if (idx + 1 < end) {
                rec_n = erec[idx + 1];
                nm_n = enm[idx + 1];
            }
            if (nm != 0.f) {
                const float4* xr = (const float4*)(x + (size_t)rec.x * DIM);
                const float4* rr = (const float4*)(relt + (size_t)rec.y * DIM);
                float4 q0 = make_float4(0.f, 0.f, 0.f, 0.f);
                float4 q1 = q0;
                for (int t = rec.z; t < rec.z + rec.w; t++) {
                    const uint2* qp = (const uint2*)(qproj + (size_t)t * DIM);
                    uint2 u0 = qp[c0];
                    float2 f0 = __half22float2(*reinterpret_cast<__half2*>(&u0.x));
                    float2 f1 = __half22float2(*reinterpret_cast<__half2*>(&u0.y));
                    q0.x += f0.x; q0.y += f0.y; q0.z += f1.x; q0.w += f1.y;
                    if (has1) {
                        uint2 u1 = qp[c1];
                        float2 g0 = __half22float2(*reinterpret_cast<__half2*>(&u1.x));
                        float2 g1 = __half22float2(*reinterpret_cast<__half2*>(&u1.y));
                        q1.x += g0.x; q1.y += g0.y; q1.z += g1.x; q1.w += g1.y;
                    }
                }
                float4 xv = xr[c0], rv = rr[c0];
                a0.x += nm * xv.x * (ALPHA * rv.x + (1.f - ALPHA) * q0.x);
                a0.y += nm * xv.y * (ALPHA * rv.y + (1.f - ALPHA) * q0.y);
                a0.z += nm * xv.z * (ALPHA * rv.z + (1.f - ALPHA) * q0.z);
                a0.w += nm * xv.w * (ALPHA * rv.w + (1.f - ALPHA) * q0.w);
                if (has1) {
                    float4 xw = xr[c1], rw = rr[c1];
                    a1.x += nm * xw.x * (ALPHA * rw.x + (1.f - ALPHA) * q1.x);
                    a1.y += nm * xw.y * (ALPHA * rw.y + (1.f - ALPHA) * q1.y);
                    a1.z += nm * xw.z * (ALPHA * rw.z + (1.f - ALPHA) * q1.z);
                    a1.w += nm * xw.w * (ALPHA * rw.w + (1.f - ALPHA) * q1.w);
                }
            }
            rec = rec_n;
            nm = nm_n;
        }
    }
    __half* ob = (d ? nouth : ninh) + (size_t)n * DIM;
    union { uint2 u; __half2 h2[2]; } s0;
    s0.h2[0] = __floats2half2_rn(a0.x, a0.y);
    s0.h2[1] = __floats2half2_rn(a0.z, a0.w);
    ((uint2*)ob)[c0] = s0.u;
    if (has1) {
        union { uint2 u; __half2 h2[2]; } s1;
        s1.h2[0] = __floats2half2_rn(a1.x, a1.y);
        s1.h2[1] = __floats2half2_rn(a1.z, a1.w);
        ((uint2*)ob)[c1] = s1.u;
    }
}

// ---------------- final batched gathers --------------------------------------
__global__ void k_gather(const float* __restrict__ xf, const float* __restrict__ rf,
                         const int* __restrict__ ent_ix, const int* __restrict__ rel_ix,
                         const int* __restrict__ quals_ix, float* __restrict__ out)
{
    int warp = (blockIdx.x * blockDim.x + threadIdx.x) >> 5;
    int lane = threadIdx.x & 31;
    int nwarp = (gridDim.x * blockDim.x) >> 5;
    const int total = NB * 14;
    for (int r = warp; r < total; r += nwarp) {
        int b = r / 14, s = r - b * 14;
        const float* srcp;
        float* dstp;
        if (s == 0)      { srcp = xf + (size_t)ent_ix[b] * DIM;  dstp = out + OFF_SUB + (size_t)b * DIM; }
        else if (s == 1) { srcp = rf + (size_t)rel_ix[b] * DIM;  dstp = out + OFF_REL + (size_t)b * DIM; }
        else if (s < 8)  { int p = s - 2;
                           srcp = xf + (size_t)quals_ix[b * 2 * QP + 2 * p + 1] * DIM;
                           dstp = out + OFF_QO + ((size_t)b * QP + p) * DIM; }
        else             { int p = s - 8;
                           srcp = rf + (size_t)quals_ix[b * 2 * QP + 2 * p] * DIM;
                           dstp = out + OFF_QR + ((size_t)b * QP + p) * DIM; }
        for (int c = lane; c < D4; c += 32)
            ((float4*)dstp)[c] = ((const float4*)srcp)[c];
    }
}

// ---------------------------------------------------------------------------

extern "C" void kernel_launch(void* const* d_in, const int* in_sizes, int n_in,
                              void* d_out, int out_size)
{
    const float* ent        = (const float*)d_in[0];
    const float* rel0       = (const float*)d_in[1];
    const float* w_in[2]    = {(const float*)d_in[2],  (const float*)d_in[7]};
    const float* w_out[2]   = {(const float*)d_in[3],  (const float*)d_in[8]};
    const float* w_loop[2]  = {(const float*)d_in[4],  (const float*)d_in[9]};
    const float* w_rel[2]   = {(const float*)d_in[5],  (const float*)d_in[10]};
    const float* w_q[2]     = {(const float*)d_in[6],  (const float*)d_in[11]};
    const float* loop_rel[2]= {(const float*)d_in[12], (const float*)d_in[13]};
    const float* bias[2]    = {(const float*)d_in[14], (const float*)d_in[15]};
    const int* ei       = (const int*)d_in[16];
    const int* et       = (const int*)d_in[17];
    const int* qu       = (const int*)d_in[18];
    const int* ent_ix   = (const int*)d_in[19];
    const int* rel_ix   = (const int*)d_in[20];
    const int* quals_ix = (const int*)d_in[21];
    float* out = (float*)d_out;

    float *x1, *r1, *dinv, *enm;
    __half *qproj, *ninh, *nouth, *wh;
    int *ecnt, *estart, *ecur, *qcnt, *qstart, *qcur, *qpos;
    int *qecnt, *qecur, *jord, *part, *psc;
    int4* erec;
    cudaGetSymbolAddress((void**)&qproj,  g_qproj);
    cudaGetSymbolAddress((void**)&ninh,   g_ninh);
    cudaGetSymbolAddress((void**)&nouth,  g_nouth);
    cudaGetSymbolAddress((void**)&x1,     g_x1);
    cudaGetSymbolAddress((void**)&r1,     g_r1);
    cudaGetSymbolAddress((void**)&dinv,   g_dinv);
    cudaGetSymbolAddress((void**)&enm,    g_enm);
    cudaGetSymbolAddress((void**)&wh,     g_wh);
    cudaGetSymbolAddress((void**)&ecnt,   gi_ecnt);
    cudaGetSymbolAddress((void**)&estart, gi_estart);
    cudaGetSymbolAddress((void**)&ecur,   gi_ecur);
    cudaGetSymbolAddress((void**)&qcnt,   gi_qcnt);
    cudaGetSymbolAddress((void**)&qstart, gi_qstart);
    cudaGetSymbolAddress((void**)&qcur,   gi_qcur);
    cudaGetSymbolAddress((void**)&qpos,   gi_qpos);
    cudaGetSymbolAddress((void**)&qecnt,  gi_qecnt);
    cudaGetSymbolAddress((void**)&qecur,  gi_qecur);
    cudaGetSymbolAddress((void**)&jord,   gi_jord);
    cudaGetSymbolAddress((void**)&erec,   gi_erec);
    cudaGetSymbolAddress((void**)&part,   gi_part);
    cudaGetSymbolAddress((void**)&psc,    gi_psc);

    // ---- fp16 weight conversion (single launch, 10 matrices) ----
    WPtrs wp;
    for (int L = 0; L < 2; L++) {
        wp.p[L * 5 + 0] = w_in[L];
        wp.p[L * 5 + 1] = w_out[L];
        wp.p[L * 5 + 2] = w_loop[L];
        wp.p[L * 5 + 3] = w_q[L];
        wp.p[L * 5 + 4] = w_rel[L];
    }
    k_convW_all<<<(int)((10L * MSZ + 255) / 256), 256>>>(wp, wh);

    // ---- CSR build + entity sort ----
    k_zero<<<256, 256>>>((float*)ecnt, 2L * NE);
    k_zero<<<512, 256>>>((float*)qcnt, 2L * NEDGE);
    k_zero<<<128, 256>>>((float*)qecnt, (long)NE);
    k_counts<<<2048, 256>>>(ei, qu, ecnt, qcnt, qecnt);

    int nbE = (2 * NE + 1023) / 1024;
    k_scan1<<<nbE, 1024>>>(ecnt, estart, part, 2 * NE);
    k_scan1<<<1, 1024>>>(part, psc, (int*)0, nbE);
    k_scan_add2<<<nbE, 1024>>>(estart, ecur, psc, 2 * NE);

    int nbQ = (2 * NEDGE + 1023) / 1024;
    k_scan1<<<nbQ, 1024>>>(qcnt, qstart, part, 2 * NEDGE);
    k_scan1<<<1, 1024>>>(part, psc, (int*)0, nbQ);
    k_scan_add2<<<nbQ, 1024>>>(qstart, qcur, psc, 2 * NEDGE);

    int nbQE = (NE + 1023) / 1024;
    k_scan1<<<nbQE, 1024>>>(qecnt, qecur, part, NE);
    k_scan1<<<1, 1024>>>(part, psc, (int*)0, nbQE);
    k_scan_add<<<nbQE, 1024>>>(qecur, psc, NE);

    k_dinv<<<512, 256>>>(ecnt, dinv);
    k_fill_qj<<<2048, 256>>>(qu, qcur, qpos, qecur, jord);
    k_fill_e<<<2048, 256>>>(ei, et, dinv, qstart, qcnt, ecur, erec, enm);

    float* xf = out + OFF_X;
    float* rf = out + OFF_R;

    for (int L = 0; L < 2; L++) {
        const float* xin = L ? (const float*)x1 : ent;
        const float* rin = L ? (const float*)r1 : rel0;
        float* xout = L ? xf : x1;
        float* rout = L ? rf : r1;

        // qproj[qpos[j]] = fp16((x[q_e[j]] ⊙ rel[q_r[j]]) @ w_q), entity-sorted rows
        k_gemm<M_QUAL><<<(QROW + BM - 1) / BM, 256>>>(
            xin, 0, 0, 0, rin, qu + QROW, qu, jord, qpos,
            wh + (size_t)(L * 5 + 3) * MSZ, 0, qproj, 0, QROW);

        // both-direction record-based CSR gather -> ninh / nouth (fp16)
        k_agg<<<(2 * NE * 32 + 255) / 256, 256>>>(
            xin, rin, estart, ecnt, erec, enm, qproj, ninh, nouth);

        // x_out = tanh(([nin|nout|x⊙loop] @ [w_in;w_out;w_loop])/3 + b)
        k_gemm<M_FUSE><<<(NE + BM - 1) / BM, 256>>>(
            0, ninh, nouth, xin, loop_rel[L], 0, 0, 0, 0,
            wh + (size_t)(L * 5 + 0) * MSZ, xout, 0, bias[L], NE);

        // r_out = r_in @ w_rel
        k_gemm<M_PLAIN><<<(NR + BM - 1) / BM, 256>>>(
            rin, 0, 0, 0, 0, 0, 0, 0, 0,
            wh + (size_t)(L * 5 + 4) * MSZ, rout, 0, 0, NR);
    }

    k_gather<<<7168, 256>>>(xf, rf, ent_ix, rel_ix, quals_ix, out);
}

// round 16
// speedup vs baseline: 1.0323x; 1.0031x over previous
#include <cuda_runtime.h>
#include <cuda_fp16.h>
#include <math.h>
#include <stdint.h>

// ---------------------------------------------------------------------------
// HypRelEncoder — round 16 (round-15 design, call-site compile fix):
//  * fp16 x SHADOW table used ONLY by k_agg (80 MB working set -> L2-resident)
//    QUAL / FUSE keep proven fp32 paths (r13 showed fp16 there hurts)
//  * layer-0 FUSE epilogue dual-writes fp32 x1 + fp16 xh (no extra pass)
//  * launch trims from r14 retained
// ---------------------------------------------------------------------------

#define NE    200000
#define DIM   200
#define D4    50          // DIM / 4
#define NEDGE 500000
#define NQ    400000
#define QROW  (2*NQ)      // 800000
#define NR    200
#define NB    4096
#define QP    6
#define ALPHA 0.8f
#define MSZ   (208*208)   // padded fp16 weight matrix size

#define OFF_SUB 0
#define OFF_REL (NB*DIM)
#define OFF_QO  (2*NB*DIM)
#define OFF_QR  (OFF_QO + NB*QP*DIM)
#define OFF_X   (OFF_QR + NB*QP*DIM)
#define OFF_R   (OFF_X + NE*DIM)

// ---------------- device scratch -------------------------------------------
__device__ __align__(16) __half g_qproj[(size_t)QROW * DIM];  // 320 MB fp16, CSR order
__device__ __align__(16) __half g_ninh [(size_t)NE * DIM];    // 80 MB fp16
__device__ __align__(16) __half g_nouth[(size_t)NE * DIM];    // 80 MB fp16
__device__ __align__(16) __half g_xh   [(size_t)NE * DIM];    // 80 MB fp16 x shadow (k_agg only)
__device__ float g_x1  [(size_t)NE * DIM];                    // 160 MB fp32 layer-1 x
__device__ float g_r1[NR * DIM];
__device__ float g_dinv[2 * NE];
__device__ __align__(16) __half g_wh[(size_t)10 * MSZ];       // padded fp16 weights
__device__ int   gi_ecnt[2 * NE];
__device__ int   gi_estart[2 * NE];
__device__ int   gi_ecur[2 * NE];
__device__ int   gi_qcnt[2 * NEDGE];
__device__ int   gi_qstart[2 * NEDGE];
__device__ int   gi_qcur[2 * NEDGE];
__device__ int   gi_qpos[2 * NQ];                // qual j -> CSR (qproj) position
__device__ int4  gi_erec[2 * NEDGE];             // (src, ty, qstart, qcnt) sorted
__device__ float g_enm [2 * NEDGE];              // per-edge norm, sorted
__device__ int   gi_part[1024];
__device__ int   gi_psc[1024];

// ---------------- small helpers --------------------------------------------
__global__ void k_zero(float* __restrict__ p, long n) {
    long i = ((long)blockIdx.x * blockDim.x + threadIdx.x) * 4;
    long st = (long)gridDim.x * blockDim.x * 4;
    float4 z = make_float4(0.f, 0.f, 0.f, 0.f);
    for (; i < n; i += st) *(float4*)(p + i) = z;
}
// fp32 -> fp16 vector convert (n multiple of 4)
__global__ void k_convH(const float* __restrict__ in, __half* __restrict__ out, long n) {
    long i = ((long)blockIdx.x * blockDim.x + threadIdx.x) * 4;
    long st = (long)gridDim.x * blockDim.x * 4;
    for (; i < n; i += st) {
        float4 v = *(const float4*)(in + i);
        union { uint2 u; __half2 h[2]; } p;
        p.h[0] = __floats2half2_rn(v.x, v.y);
        p.h[1] = __floats2half2_rn(v.z, v.w);
        *(uint2*)(out + i) = p.u;
    }
}

// fused histograms: edge-dst counts + qual-eid counts
__global__ void k_counts(const int* __restrict__ ei, const int* __restrict__ qu,
                         int* __restrict__ ecnt, int* __restrict__ qcnt) {
    int i = blockIdx.x * blockDim.x + threadIdx.x;
    int st = gridDim.x * blockDim.x;
    for (; i < 2 * NEDGE; i += st) {
        atomicAdd(&ecnt[((i >= NEDGE) ? NE : 0) + ei[2 * NEDGE + i]], 1);
        if (i < 2 * NQ)
            atomicAdd(&qcnt[((i >= NQ) ? NEDGE : 0) + qu[2 * QROW + i]], 1);
    }
}
__global__ void k_fill_q(const int* __restrict__ qu, int* __restrict__ cur,
                         int* __restrict__ qpos) {
    int j = blockIdx.x * blockDim.x + threadIdx.x;
    int st = gridDim.x * blockDim.x;
    for (; j < 2 * NQ; j += st) {
        int b = ((j >= NQ) ? NEDGE : 0) + qu[2 * QROW + j];
        qpos[j] = atomicAdd(&cur[b], 1);
    }
}
__global__ void k_fill_e(const int* __restrict__ ei, const int* __restrict__ et,
                         const float* __restrict__ dinv,
                         const int* __restrict__ qstart, const int* __restrict__ qcnt,
                         int* __restrict__ cur,
                         int4* __restrict__ erec, float* __restrict__ enm) {
    int i = blockIdx.x * blockDim.x + threadIdx.x;
    int st = gridDim.x * blockDim.x;
    for (; i < 2 * NEDGE; i += st) {
        int d = (i >= NEDGE) ? 1 : 0;
        int e = i - d * NEDGE;
        int src = ei[i];
        int dst = ei[2 * NEDGE + i];
        int pos = atomicAdd(&cur[d * NE + dst], 1);
        int4 r;
        r.x = src;
        r.y = et[i];
        r.z = qstart[d * NEDGE + e];
        r.w = qcnt[d * NEDGE + e];
        erec[pos] = r;
        enm[pos] = dinv[d * NE + src] * dinv[d * NE + dst];
    }
}
__global__ void k_dinv(const int* __restrict__ cnt, float* __restrict__ dinv) {
    int i = blockIdx.x * blockDim.x + threadIdx.x;
    int st = gridDim.x * blockDim.x;
    for (; i < 2 * NE; i += st) {
        int d = (i >= NE) ? 1 : 0;
        int n = i - d * NE;
        int c = cnt[(1 - d) * NE + n];
        dinv[i] = (c > 0) ? rsqrtf((float)c) : 0.f;
    }
}

// all 10 weight matrices fp32 [200][200] -> fp16 zero-padded [208][208], 1 launch
struct WPtrs { const float* p[10]; };
__global__ void k_convW_all(WPtrs ws, __half* __restrict__ dst) {
    long t = (long)blockIdx.x * blockDim.x + threadIdx.x;
    if (t >= 10L * MSZ) return;
    int m = (int)(t / MSZ);
    int r = (int)(t - (long)m * MSZ);
    int k = r / 208, n = r - k * 208;
    float v = (k < DIM && n < DIM) ? ws.p[m][k * DIM + n] : 0.f;
    dst[t] = __float2half_rn(v);
}

// ---------------- two-level exclusive scan ----------------------------------
__global__ void k_scan1(const int* __restrict__ in, int* __restrict__ out,
                        int* __restrict__ part, int n) {
    __shared__ int s[1024];
    int t = threadIdx.x;
    int g = blockIdx.x * 1024 + t;
    int v = (g < n) ? in[g] : 0;
    s[t] = v;
    __syncthreads();
    for (int off = 1; off < 1024; off <<= 1) {
        int u = (t >= off) ? s[t - off] : 0;
        __syncthreads();
        s[t] += u;
        __syncthreads();
    }
    if (g < n) out[g] = s[t] - v;
    if (t == 1023 && part) part[blockIdx.x] = s[1023];
}
// adds block offsets AND writes the cursor copy (replaces memcpy)
__global__ void k_scan_add2(int* __restrict__ out, int* __restrict__ cur,
                            const int* __restrict__ psc, int n) {
    int g = blockIdx.x * 1024 + threadIdx.x;
    if (g < n) {
        int v = out[g] + psc[blockIdx.x];
        out[g] = v;
        cur[g] = v;
    }
}

// ---------------- fp16 helpers ----------------------------------------------
__device__ __forceinline__ float4 h4f(uint2 u) {
    float2 a = __half22float2(*reinterpret_cast<__half2*>(&u.x));
    float2 b = __half22float2(*reinterpret_cast<__half2*>(&u.y));
    return make_float4(a.x, a.y, b.x, b.y);
}

// ---------------- fp16 tensor-core GEMM --------------------------------------
// C[rows,200] = compose(A)[rows,K] @ W[K,200]; K sections of 200.
// BM=64, 8 warps (4xM, 2xN); full-K A tile; double-buffered reg-staged W.

enum { M_QUAL = 0, M_FUSE = 1, M_PLAIN = 2 };

#define BM  64
#define AST 216       // half stride (432B = 27*16)
#define WST 216

__device__ __forceinline__ uint32_t s2u(const void* p) {
    return (uint32_t)__cvta_generic_to_shared(p);
}
__device__ __forceinline__ void mma16(float* c, uint32_t a0, uint32_t a1,
                                      uint32_t a2, uint32_t a3,
                                      uint32_t b0, uint32_t b1) {
    asm volatile(
        "mma.sync.aligned.m16n8k16.row.col.f32.f16.f16.f32 "
        "{%0,%1,%2,%3},{%4,%5,%6,%7},{%8,%9},{%0,%1,%2,%3};"
        : "+f"(c[0]), "+f"(c[1]), "+f"(c[2]), "+f"(c[3])
        : "r"(a0), "r"(a1), "r"(a2), "r"(a3), "r"(b0), "r"(b1));
}

template <int MODE>
__global__ void __launch_bounds__(256, 2)
k_gemm(const float* __restrict__ A,      // QUAL: x table | PLAIN: rows
       const __half* __restrict__ hA,    // FUSE: nin (fp16)
       const __half* __restrict__ hB2,   // FUSE: nout (fp16)
       const float* __restrict__ C3,     // FUSE: x (loop section)
       const float* __restrict__ relt,   // QUAL: rel table | FUSE: loop_rel
       const int* __restrict__ qe, const int* __restrict__ qr,
       const int* __restrict__ opos,     // QUAL: output row permutation
       const __half* __restrict__ Wh,    // fp16 padded; FUSE: 3 consecutive
       float* __restrict__ out,          // FUSE / PLAIN output
       __half* __restrict__ hqout,       // QUAL output (fp16)
       __half* __restrict__ hx2,         // FUSE: optional fp16 shadow dual-write
       const float* __restrict__ bias,   // FUSE
       int nrows)
{
    __shared__ __align__(16) __half As[BM * AST];
    __shared__ __align__(16) __half Wb[2][16 * WST];
    const int tid = threadIdx.x;
    const int wid = tid >> 5, lane = tid & 31;
    const int wm = wid >> 1, wn = wid & 1;
    const int r4 = lane >> 2, kq = lane & 3;
    const int row0 = blockIdx.x * BM;
    const int NSEC = (MODE == M_FUSE) ? 3 : 1;
    const int k0a = tid / 26, sg0 = tid - k0a * 26;
    const int s1 = tid + 256;
    const int k1a = s1 / 26, sg1 = s1 - k1a * 26;
    const bool h2nd = (tid < 160);

    float acc[13][4];
#pragma unroll
    for (int f = 0; f < 13; f++)
        acc[f][0] = acc[f][1] = acc[f][2] = acc[f][3] = 0.f;

    for (int sec = 0; sec < NSEC; sec++) {
        __syncthreads();   // prev section's MMA reads of As/Wb complete
        // ---- fill full-K A tile (fp16), warp-per-row ----
        for (int rr = wid; rr < BM; rr += 8) {
            int gr = row0 + rr;
            bool valid = gr < nrows;
            if (MODE == M_FUSE && sec < 2) {
                const __half* hrow = (sec == 0 ? hA : hB2) + (size_t)gr * DIM;
#pragma unroll
                for (int h = 0; h < 2; h++) {
                    int k4 = lane + 32 * h;
                    if (k4 >= 54) continue;
                    uint2 v = make_uint2(0, 0);
                    if (valid && k4 < D4)
                        v = ((const uint2*)hrow)[k4];
                    *reinterpret_cast<uint2*>(&As[rr * AST + k4 * 4]) = v;
                }
            } else {
                const float4 *p1 = 0, *p2 = 0;
                if (valid) {
                    if (MODE == M_QUAL) {
                        p1 = (const float4*)(A + (size_t)qe[gr] * DIM);
                        p2 = (const float4*)(relt + (size_t)qr[gr] * DIM);
                    } else if (MODE == M_FUSE) {       // sec == 2: loop section
                        p1 = (const float4*)(C3 + (size_t)gr * DIM);
                        p2 = (const float4*)relt;
                    } else {
                        p1 = (const float4*)(A + (size_t)gr * DIM);
                    }
                }
#pragma unroll
                for (int h = 0; h < 2; h++) {
                    int k4 = lane + 32 * h;
                    if (k4 >= 54) continue;          // 54*4 = 216 = AST
                    float4 v = make_float4(0.f, 0.f, 0.f, 0.f);
                    if (valid && k4 < D4) {
                        v = p1[k4];
                        if (MODE == M_QUAL || MODE == M_FUSE) {
                            float4 r = p2[k4];
                            v.x *= r.x; v.y *= r.y; v.z *= r.z; v.w *= r.w;
                        }
                    }
                    union { uint2 u; __half2 h2[2]; } pk;
                    pk.h2[0] = __floats2half2_rn(v.x, v.y);
                    pk.h2[1] = __floats2half2_rn(v.z, v.w);
                    *reinterpret_cast<uint2*>(&As[rr * AST + k4 * 4]) = pk.u;
                }
            }
        }
        const __half* Wg = Wh + (size_t)sec * MSZ;
        const uint4* Wg4 = (const uint4*)Wg;

        uint4 w0 = Wg4[tid];
        uint4 w1 = h2nd ? Wg4[s1] : make_uint4(0, 0, 0, 0);
        *(uint4*)&Wb[0][k0a * WST + sg0 * 8] = w0;
        if (h2nd) *(uint4*)&Wb[0][k1a * WST + sg1 * 8] = w1;
        w0 = Wg4[416 + tid];
        if (h2nd) w1 = Wg4[416 + s1];
        __syncthreads();        // As + buf0 visible

        for (int ks = 0; ks < 13; ks++) {
            const __half* wb = Wb[ks & 1];
            uint32_t a0, a1, a2, a3;
            uint32_t aaddr = s2u(&As[(wm * 16 + (lane & 15)) * AST
                                     + ks * 16 + ((lane >> 4) << 3)]);
            asm volatile("ldmatrix.sync.aligned.m8n8.x4.shared.b16 {%0,%1,%2,%3}, [%4];"
                         : "=r"(a0), "=r"(a1), "=r"(a2), "=r"(a3) : "r"(aaddr));
            int brow = ((lane >> 3) & 1) * 8 + (lane & 7);
#pragma unroll
            for (int fp = 0; fp < 6; fp++) {
                int n0 = wn * 104 + fp * 16;
                uint32_t b0, b1, b2, b3;
                uint32_t baddr = s2u(&wb[brow * WST + n0 + ((lane >> 4) << 3)]);
                asm volatile("ldmatrix.sync.aligned.m8n8.x4.trans.shared.b16 "
                             "{%0,%1,%2,%3}, [%4];"
                             : "=r"(b0), "=r"(b1), "=r"(b2), "=r"(b3) : "r"(baddr));
                mma16(acc[2 * fp], a0, a1, a2, a3, b0, b1);
                mma16(acc[2 * fp + 1], a0, a1, a2, a3, b2, b3);
            }
            {
                int n0 = wn * 104 + 96;
                uint32_t b0, b1;
                uint32_t baddr = s2u(&wb[brow * WST + n0]);
                asm volatile("ldmatrix.sync.aligned.m8n8.x2.trans.shared.b16 "
                             "{%0,%1}, [%2];"
                             : "=r"(b0), "=r"(b1) : "r"(baddr));
                mma16(acc[12], a0, a1, a2, a3, b0, b1);
            }
            if (ks < 12) {
                __half* db = Wb[(ks + 1) & 1];
                *(uint4*)&db[k0a * WST + sg0 * 8] = w0;
                if (h2nd) *(uint4*)&db[k1a * WST + sg1 * 8] = w1;
                if (ks < 11) {
                    w0 = Wg4[(size_t)(ks + 2) * 416 + tid];
                    if (h2nd) w1 = Wg4[(size_t)(ks + 2) * 416 + s1];
                }
                __syncthreads();
            }
        }
    }

    // ---- epilogue ----
    int gr0 = row0 + wm * 16 + r4;
    int orow[2];
#pragma unroll
    for (int half = 0; half < 2; half++) {
        int gr = gr0 + 8 * half;
        orow[half] = (gr < nrows) ? ((MODE == M_QUAL) ? opos[gr] : gr) : -1;
    }
#pragma unroll
    for (int f = 0; f < 13; f++) {
        int col = wn * 104 + 8 * f + 2 * kq;
        if (col >= DIM) continue;
#pragma unroll
        for (int half = 0; half < 2; half++) {
            if (orow[half] < 0) continue;
            size_t o = (size_t)orow[half] * DIM + col;
            float v0 = acc[f][2 * half], v1 = acc[f][2 * half + 1];
            if (MODE == M_QUAL) {
                *reinterpret_cast<__half2*>(&hqout[o]) = __floats2half2_rn(v0, v1);
            } else if (MODE == M_FUSE) {
                float t0 = tanhf(v0 * (1.f / 3.f) + bias[col]);
                float t1 = tanhf(v1 * (1.f / 3.f) + bias[col + 1]);
                out[o] = t0; out[o + 1] = t1;
                if (hx2)
                    *reinterpret_cast<__half2*>(&hx2[o]) = __floats2half2_rn(t0, t1);
            } else {
                out[o] = v0; out[o + 1] = v1;
            }
        }
    }
}

// ---------------- CSR gather aggregation (fp16 x shadow + fp16 qproj) --------
__global__ void __launch_bounds__(256)
k_agg(const __half* __restrict__ xh, const float* __restrict__ relt,
      const int* __restrict__ e_start, const int* __restrict__ e_cnt,
      const int4* __restrict__ erec, const float* __restrict__ enm,
      const __half* __restrict__ qproj,
      __half* __restrict__ ninh, __half* __restrict__ nouth)
{
    int w = (blockIdx.x * blockDim.x + threadIdx.x) >> 5;
    int lane = threadIdx.x & 31;
    if (w >= 2 * NE) return;
    int d = (w >= NE) ? 1 : 0;
    int n = w - d * NE;

    int c0 = lane;
    int c1 = lane + 32;
    bool has1 = (c1 < D4);

    float4 a0 = make_float4(0.f, 0.f, 0.f, 0.f);
    float4 a1 = a0;

    int beg = e_start[w];
    int end = beg + e_cnt[w];
    if (beg < end) {
        int4 rec = erec[beg];
        float nm = enm[beg];
        for (int idx = beg; idx < end; idx++) {
            int4 rec_n = rec;
            float nm_n = nm;
            if (idx + 1 < end) {
                rec_n = erec[idx + 1];
                nm_n = enm[idx + 1];
            }
            if (nm != 0.f) {
                const uint2* xr = (const uint2*)(xh + (size_t)rec.x * DIM);
                const float4* rr = (const float4*)(relt + (size_t)rec.y * DIM);
                float4 q0 = make_float4(0.f, 0.f, 0.f, 0.f);
                float4 q1 = q0;
                for (int t = rec.z; t < rec.z + rec.w; t++) {
                    const uint2* qp = (const uint2*)(qproj + (size_t)t * DIM);
                    float4 f = h4f(qp[c0]);
                    q0.x += f.x; q0.y += f.y; q0.z += f.z; q0.w += f.w;
                    if (has1) {
                        float4 g = h4f(qp[c1]);
                        q1.x += g.x; q1.y += g.y; q1.z += g.z; q1.w += g.w;
                    }
                }
                float4 xv = h4f(xr[c0]), rv = rr[c0];
                a0.x += nm * xv.x * (ALPHA * rv.x + (1.f - ALPHA) * q0.x);
                a0.y += nm * xv.y * (ALPHA * rv.y + (1.f - ALPHA) * q0.y);
                a0.z += nm * xv.z * (ALPHA * rv.z + (1.f - ALPHA) * q0.z);
                a0.w += nm * xv.w * (ALPHA * rv.w + (1.f - ALPHA) * q0.w);
                if (has1) {
                    float4 xw = h4f(xr[c1]), rw = rr[c1];
                    a1.x += nm * xw.x * (ALPHA * rw.x + (1.f - ALPHA) * q1.x);
                    a1.y += nm * xw.y * (ALPHA * rw.y + (1.f - ALPHA) * q1.y);
                    a1.z += nm * xw.z * (ALPHA * rw.z + (1.f - ALPHA) * q1.z);
                    a1.w += nm * xw.w * (ALPHA * rw.w + (1.f - ALPHA) * q1.w);
                }
            }
            rec = rec_n;
            nm = nm_n;
        }
    }
    __half* ob = (d ? nouth : ninh) + (size_t)n * DIM;
    union { uint2 u; __half2 h2[2]; } s0;
    s0.h2[0] = __floats2half2_rn(a0.x, a0.y);
    s0.h2[1] = __floats2half2_rn(a0.z, a0.w);
    ((uint2*)ob)[c0] = s0.u;
    if (has1) {
        union { uint2 u; __half2 h2[2]; } s1;
        s1.h2[0] = __floats2half2_rn(a1.x, a1.y);
        s1.h2[1] = __floats2half2_rn(a1.z, a1.w);
        ((uint2*)ob)[c1] = s1.u;
    }
}

// ---------------- final batched gathers --------------------------------------
__global__ void k_gather(const float* __restrict__ xf, const float* __restrict__ rf,
                         const int* __restrict__ ent_ix, const int* __restrict__ rel_ix,
                         const int* __restrict__ quals_ix, float* __restrict__ out)
{
    int warp = (blockIdx.x * blockDim.x + threadIdx.x) >> 5;
    int lane = threadIdx.x & 31;
    int nwarp = (gridDim.x * blockDim.x) >> 5;
    const int total = NB * 14;
    for (int r = warp; r < total; r += nwarp) {
        int b = r / 14, s = r - b * 14;
        const float* srcp;
        float* dstp;
        if (s == 0)      { srcp = xf + (size_t)ent_ix[b] * DIM;  dstp = out + OFF_SUB + (size_t)b * DIM; }
        else if (s == 1) { srcp = rf + (size_t)rel_ix[b] * DIM;  dstp = out + OFF_REL + (size_t)b * DIM; }
        else if (s < 8)  { int p = s - 2;
                           srcp = xf + (size_t)quals_ix[b * 2 * QP + 2 * p + 1] * DIM;
                           dstp = out + OFF_QO + ((size_t)b * QP + p) * DIM; }
        else             { int p = s - 8;
                           srcp = rf + (size_t)quals_ix[b * 2 * QP + 2 * p] * DIM;
                           dstp = out + OFF_QR + ((size_t)b * QP + p) * DIM; }
        for (int c = lane; c < D4; c += 32)
            ((float4*)dstp)[c] = ((const float4*)srcp)[c];
    }
}

// ---------------------------------------------------------------------------

extern "C" void kernel_launch(void* const* d_in, const int* in_sizes, int n_in,
                              void* d_out, int out_size)
{
    const float* ent        = (const float*)d_in[0];
    const float* rel0       = (const float*)d_in[1];
    const float* w_in[2]    = {(const float*)d_in[2],  (const float*)d_in[7]};
    const float* w_out[2]   = {(const float*)d_in[3],  (const float*)d_in[8]};
    const float* w_loop[2]  = {(const float*)d_in[4],  (const float*)d_in[9]};
    const float* w_rel[2]   = {(const float*)d_in[5],  (const float*)d_in[10]};
    const float* w_q[2]     = {(const float*)d_in[6],  (const float*)d_in[11]};
    const float* loop_rel[2]= {(const float*)d_in[12], (const float*)d_in[13]};
    const float* bias[2]    = {(const float*)d_in[14], (const float*)d_in[15]};
    const int* ei       = (const int*)d_in[16];
    const int* et       = (const int*)d_in[17];
    const int* qu       = (const int*)d_in[18];
    const int* ent_ix   = (const int*)d_in[19];
    const int* rel_ix   = (const int*)d_in[20];
    const int* quals_ix = (const int*)d_in[21];
    float* out = (float*)d_out;

    float *x1, *r1, *dinv, *enm;
    __half *qproj, *ninh, *nouth, *xh, *wh;
    int *ecnt, *estart, *ecur, *qcnt, *qstart, *qcur, *qpos, *part, *psc;
    int4* erec;
    cudaGetSymbolAddress((void**)&qproj,  g_qproj);
    cudaGetSymbolAddress((void**)&ninh,   g_ninh);
    cudaGetSymbolAddress((void**)&nouth,  g_nouth);
    cudaGetSymbolAddress((void**)&xh,     g_xh);
    cudaGetSymbolAddress((void**)&x1,     g_x1);
    cudaGetSymbolAddress((void**)&r1,     g_r1);
    cudaGetSymbolAddress((void**)&dinv,   g_dinv);
    cudaGetSymbolAddress((void**)&enm,    g_enm);
    cudaGetSymbolAddress((void**)&wh,     g_wh);
    cudaGetSymbolAddress((void**)&ecnt,   gi_ecnt);
    cudaGetSymbolAddress((void**)&estart, gi_estart);
    cudaGetSymbolAddress((void**)&ecur,   gi_ecur);
    cudaGetSymbolAddress((void**)&qcnt,   gi_qcnt);
    cudaGetSymbolAddress((void**)&qstart, gi_qstart);
    cudaGetSymbolAddress((void**)&qcur,   gi_qcur);
    cudaGetSymbolAddress((void**)&qpos,   gi_qpos);
    cudaGetSymbolAddress((void**)&erec,   gi_erec);
    cudaGetSymbolAddress((void**)&part,   gi_part);
    cudaGetSymbolAddress((void**)&psc,    gi_psc);

    // ---- fp16 weight conversion (single launch, 10 matrices) ----
    WPtrs wp;
    for (int L = 0; L < 2; L++) {
        wp.p[L * 5 + 0] = w_in[L];
        wp.p[L * 5 + 1] = w_out[L];
        wp.p[L * 5 + 2] = w_loop[L];
        wp.p[L * 5 + 3] = w_q[L];
        wp.p[L * 5 + 4] = w_rel[L];
    }
    k_convW_all<<<(int)((10L * MSZ + 255) / 256), 256>>>(wp, wh);

    // ---- CSR build ----
    k_zero<<<256, 256>>>((float*)ecnt, 2L * NE);
    k_zero<<<512, 256>>>((float*)qcnt, 2L * NEDGE);
    k_counts<<<2048, 256>>>(ei, qu, ecnt, qcnt);

    int nbE = (2 * NE + 1023) / 1024;
    k_scan1<<<nbE, 1024>>>(ecnt, estart, part, 2 * NE);
    k_scan1<<<1, 1024>>>(part, psc, (int*)0, nbE);
    k_scan_add2<<<nbE, 1024>>>(estart, ecur, psc, 2 * NE);

    int nbQ = (2 * NEDGE + 1023) / 1024;
    k_scan1<<<nbQ, 1024>>>(qcnt, qstart, part, 2 * NEDGE);
    k_scan1<<<1, 1024>>>(part, psc, (int*)0, nbQ);
    k_scan_add2<<<nbQ, 1024>>>(qstart, qcur, psc, 2 * NEDGE);

    k_dinv<<<512, 256>>>(ecnt, dinv);
    k_fill_q<<<2048, 256>>>(qu, qcur, qpos);
    k_fill_e<<<2048, 256>>>(ei, et, dinv, qstart, qcnt, ecur, erec, enm);

    // fp16 x shadow for layer-0 k_agg
    k_convH<<<4096, 256>>>(ent, xh, (long)NE * DIM);

    float* xf = out + OFF_X;
    float* rf = out + OFF_R;

    for (int L = 0; L < 2; L++) {
        const float* xin = L ? (const float*)x1 : ent;
        const float* rin = L ? (const float*)r1 : rel0;
        float* xout = L ? xf : x1;
        float* rout = L ? rf : r1;

        // qproj[qpos[j]] = fp16((x[q_e[j]] ⊙ rel[q_r[j]]) @ w_q)
        k_gemm<M_QUAL><<<(QROW + BM - 1) / BM, 256>>>(
            xin, 0, 0, 0, rin, qu + QROW, qu, qpos,
            wh + (size_t)(L * 5 + 3) * MSZ, 0, qproj, 0, 0, QROW);

        // both-direction record-based CSR gather (fp16 x shadow) -> nin/nout
        k_agg<<<(2 * NE * 32 + 255) / 256, 256>>>(
            xh, rin, estart, ecnt, erec, enm, qproj, ninh, nouth);

        // x_out = tanh(([nin|nout|x⊙loop] @ [w_in;w_out;w_loop])/3 + b)
        // layer 0 also dual-writes fp16 shadow xh for layer-1 k_agg
        k_gemm<M_FUSE><<<(NE + BM - 1) / BM, 256>>>(
            0, ninh, nouth, xin, loop_rel[L], 0, 0, 0,
            wh + (size_t)(L * 5 + 0) * MSZ, xout, 0,
            L ? (__half*)0 : xh, bias[L], NE);

        // r_out = r_in @ w_rel
        k_gemm<M_PLAIN><<<(NR + BM - 1) / BM, 256>>>(
            rin, 0, 0, 0, 0, 0, 0, 0,
            wh + (size_t)(L * 5 + 4) * MSZ, rout, 0, 0, 0, NR);
    }

    k_gather<<<7168, 256>>>(xf, rf, ent_ix, rel_ix, quals_ix, out);
}

// round 17
// speedup vs baseline: 1.2026x; 1.1650x over previous
#include <cuda_runtime.h>
#include <cuda_fp16.h>
#include <math.h>
#include <stdint.h>

// ---------------------------------------------------------------------------
// HypRelEncoder — round 17 (fp16-only inter-stage x, LEAN fills):
//  * single fp16 x table (xh) between layers; fp32 x1 buffer DELETED
//  * QUAL / FUSE-loop fills: uint4 LDG.128 + __hmul2 (fewer instrs than fp32)
//  * fp16 rel table rh + fp16 loop_rel lrh for composition
//  * k_agg / CSR build / W pipeline unchanged from round 16
// ---------------------------------------------------------------------------

#define NE    200000
#define DIM   200
#define D4    50          // DIM / 4
#define NEDGE 500000
#define NQ    400000
#define QROW  (2*NQ)      // 800000
#define NR    200
#define NB    4096
#define QP    6
#define ALPHA 0.8f
#define MSZ   (208*208)   // padded fp16 weight matrix size

#define OFF_SUB 0
#define OFF_REL (NB*DIM)
#define OFF_QO  (2*NB*DIM)
#define OFF_QR  (OFF_QO + NB*QP*DIM)
#define OFF_X   (OFF_QR + NB*QP*DIM)
#define OFF_R   (OFF_X + NE*DIM)

// ---------------- device scratch -------------------------------------------
__device__ __align__(16) __half g_qproj[(size_t)QROW * DIM];  // 320 MB fp16, CSR order
__device__ __align__(16) __half g_ninh [(size_t)NE * DIM];    // 80 MB fp16
__device__ __align__(16) __half g_nouth[(size_t)NE * DIM];    // 80 MB fp16
__device__ __align__(16) __half g_xh   [(size_t)NE * DIM];    // 80 MB fp16 x (inter-stage)
__device__ __align__(16) __half g_rh   [NR * DIM];            // fp16 rel table
__device__ __align__(16) __half g_lrh  [2 * 256];             // fp16 loop_rel (per layer)
__device__ float g_r1[NR * DIM];
__device__ float g_dinv[2 * NE];
__device__ __align__(16) __half g_wh[(size_t)10 * MSZ];       // padded fp16 weights
__device__ int   gi_ecnt[2 * NE];
__device__ int   gi_estart[2 * NE];
__device__ int   gi_ecur[2 * NE];
__device__ int   gi_qcnt[2 * NEDGE];
__device__ int   gi_qstart[2 * NEDGE];
__device__ int   gi_qcur[2 * NEDGE];
__device__ int   gi_qpos[2 * NQ];                // qual j -> CSR (qproj) position
__device__ int4  gi_erec[2 * NEDGE];             // (src, ty, qstart, qcnt) sorted
__device__ float g_enm [2 * NEDGE];              // per-edge norm, sorted
__device__ int   gi_part[1024];
__device__ int   gi_psc[1024];

// ---------------- small helpers --------------------------------------------
__global__ void k_zero(float* __restrict__ p, long n) {
    long i = ((long)blockIdx.x * blockDim.x + threadIdx.x) * 4;
    long st = (long)gridDim.x * blockDim.x * 4;
    float4 z = make_float4(0.f, 0.f, 0.f, 0.f);
    for (; i < n; i += st) *(float4*)(p + i) = z;
}
// fp32 -> fp16 vector convert (n multiple of 4)
__global__ void k_convH(const float* __restrict__ in, __half* __restrict__ out, long n) {
    long i = ((long)blockIdx.x * blockDim.x + threadIdx.x) * 4;
    long st = (long)gridDim.x * blockDim.x * 4;
    for (; i < n; i += st) {
        float4 v = *(const float4*)(in + i);
        union { uint2 u; __half2 h[2]; } p;
        p.h[0] = __floats2half2_rn(v.x, v.y);
        p.h[1] = __floats2half2_rn(v.z, v.w);
        *(uint2*)(out + i) = p.u;
    }
}

// fused histograms: edge-dst counts + qual-eid counts
__global__ void k_counts(const int* __restrict__ ei, const int* __restrict__ qu,
                         int* __restrict__ ecnt, int* __restrict__ qcnt) {
    int i = blockIdx.x * blockDim.x + threadIdx.x;
    int st = gridDim.x * blockDim.x;
    for (; i < 2 * NEDGE; i += st) {
        atomicAdd(&ecnt[((i >= NEDGE) ? NE : 0) + ei[2 * NEDGE + i]], 1);
        if (i < 2 * NQ)
            atomicAdd(&qcnt[((i >= NQ) ? NEDGE : 0) + qu[2 * QROW + i]], 1);
    }
}
__global__ void k_fill_q(const int* __restrict__ qu, int* __restrict__ cur,
                         int* __restrict__ qpos) {
    int j = blockIdx.x * blockDim.x + threadIdx.x;
    int st = gridDim.x * blockDim.x;
    for (; j < 2 * NQ; j += st) {
        int b = ((j >= NQ) ? NEDGE : 0) + qu[2 * QROW + j];
        qpos[j] = atomicAdd(&cur[b], 1);
    }
}
__global__ void k_fill_e(const int* __restrict__ ei, const int* __restrict__ et,
                         const float* __restrict__ dinv,
                         const int* __restrict__ qstart, const int* __restrict__ qcnt,
                         int* __restrict__ cur,
                         int4* __restrict__ erec, float* __restrict__ enm) {
    int i = blockIdx.x * blockDim.x + threadIdx.x;
    int st = gridDim.x * blockDim.x;
    for (; i < 2 * NEDGE; i += st) {
        int d = (i >= NEDGE) ? 1 : 0;
        int e = i - d * NEDGE;
        int src = ei[i];
        int dst = ei[2 * NEDGE + i];
        int pos = atomicAdd(&cur[d * NE + dst], 1);
        int4 r;
        r.x = src;
        r.y = et[i];
        r.z = qstart[d * NEDGE + e];
        r.w = qcnt[d * NEDGE + e];
        erec[pos] = r;
        enm[pos] = dinv[d * NE + src] * dinv[d * NE + dst];
    }
}
__global__ void k_dinv(const int* __restrict__ cnt, float* __restrict__ dinv) {
    int i = blockIdx.x * blockDim.x + threadIdx.x;
    int st = gridDim.x * blockDim.x;
    for (; i < 2 * NE; i += st) {
        int d = (i >= NE) ? 1 : 0;
        int n = i - d * NE;
        int c = cnt[(1 - d) * NE + n];
        dinv[i] = (c > 0) ? rsqrtf((float)c) : 0.f;
    }
}

// all 10 weight matrices fp32 [200][200] -> fp16 zero-padded [208][208], 1 launch
struct WPtrs { const float* p[10]; };
__global__ void k_convW_all(WPtrs ws, __half* __restrict__ dst) {
    long t = (long)blockIdx.x * blockDim.x + threadIdx.x;
    if (t >= 10L * MSZ) return;
    int m = (int)(t / MSZ);
    int r = (int)(t - (long)m * MSZ);
    int k = r / 208, n = r - k * 208;
    float v = (k < DIM && n < DIM) ? ws.p[m][k * DIM + n] : 0.f;
    dst[t] = __float2half_rn(v);
}

// ---------------- two-level exclusive scan ----------------------------------
__global__ void k_scan1(const int* __restrict__ in, int* __restrict__ out,
                        int* __restrict__ part, int n) {
    __shared__ int s[1024];
    int t = threadIdx.x;
    int g = blockIdx.x * 1024 + t;
    int v = (g < n) ? in[g] : 0;
    s[t] = v;
    __syncthreads();
    for (int off = 1; off < 1024; off <<= 1) {
        int u = (t >= off) ? s[t - off] : 0;
        __syncthreads();
        s[t] += u;
        __syncthreads();
    }
    if (g < n) out[g] = s[t] - v;
    if (t == 1023 && part) part[blockIdx.x] = s[1023];
}
// adds block offsets AND writes the cursor copy (replaces memcpy)
__global__ void k_scan_add2(int* __restrict__ out, int* __restrict__ cur,
                            const int* __restrict__ psc, int n) {
    int g = blockIdx.x * 1024 + threadIdx.x;
    if (g < n) {
        int v = out[g] + psc[blockIdx.x];
        out[g] = v;
        cur[g] = v;
    }
}

// ---------------- fp16 helpers ----------------------------------------------
__device__ __forceinline__ float4 h4f(uint2 u) {
    float2 a = __half22float2(*reinterpret_cast<__half2*>(&u.x));
    float2 b = __half22float2(*reinterpret_cast<__half2*>(&u.y));
    return make_float4(a.x, a.y, b.x, b.y);
}

// ---------------- fp16 tensor-core GEMM --------------------------------------
// C[rows,200] = compose(A)[rows,K] @ W[K,200]; K sections of 200.
// BM=64, 8 warps (4xM, 2xN); full-K A tile; double-buffered reg-staged W.

enum { M_QUAL = 0, M_FUSE = 1, M_PLAIN = 2 };

#define BM  64
#define AST 216       // half stride (432B = 27*16)
#define WST 216

__device__ __forceinline__ uint32_t s2u(const void* p) {
    return (uint32_t)__cvta_generic_to_shared(p);
}
__device__ __forceinline__ void mma16(float* c, uint32_t a0, uint32_t a1,
                                      uint32_t a2, uint32_t a3,
                                      uint32_t b0, uint32_t b1) {
    asm volatile(
        "mma.sync.aligned.m16n8k16.row.col.f32.f16.f16.f32 "
        "{%0,%1,%2,%3},{%4,%5,%6,%7},{%8,%9},{%0,%1,%2,%3};"
        : "+f"(c[0]), "+f"(c[1]), "+f"(c[2]), "+f"(c[3])
        : "r"(a0), "r"(a1), "r"(a2), "r"(a3), "r"(b0), "r"(b1));
}

template <int MODE>
__global__ void __launch_bounds__(256, 2)
k_gemm(const float* __restrict__ A,      // PLAIN: fp32 rows
       const __half* __restrict__ hA,    // FUSE: nin (fp16)
       const __half* __restrict__ hB2,   // FUSE: nout (fp16)
       const __half* __restrict__ hX,    // QUAL: x table | FUSE: loop x source
       const __half* __restrict__ hR,    // QUAL: rel table | FUSE: loop_rel fp16
       const int* __restrict__ qe, const int* __restrict__ qr,
       const int* __restrict__ opos,     // QUAL: output row permutation
       const __half* __restrict__ Wh,    // fp16 padded; FUSE: 3 consecutive
       float* __restrict__ out,          // FUSE(layer1) / PLAIN output
       __half* __restrict__ hqout,       // QUAL output (fp16)
       __half* __restrict__ hx2,         // FUSE: optional fp16 x output
       const float* __restrict__ bias,   // FUSE
       int nrows)
{
    __shared__ __align__(16) __half As[BM * AST];
    __shared__ __align__(16) __half Wb[2][16 * WST];
    const int tid = threadIdx.x;
    const int wid = tid >> 5, lane = tid & 31;
    const int wm = wid >> 1, wn = wid & 1;
    const int r4 = lane >> 2, kq = lane & 3;
    const int row0 = blockIdx.x * BM;
    const int NSEC = (MODE == M_FUSE) ? 3 : 1;
    const int k0a = tid / 26, sg0 = tid - k0a * 26;
    const int s1 = tid + 256;
    const int k1a = s1 / 26, sg1 = s1 - k1a * 26;
    const bool h2nd = (tid < 160);

    float acc[13][4];
#pragma unroll
    for (int f = 0; f < 13; f++)
        acc[f][0] = acc[f][1] = acc[f][2] = acc[f][3] = 0.f;

    for (int sec = 0; sec < NSEC; sec++) {
        __syncthreads();   // prev section's MMA reads of As/Wb complete
        // ---- fill full-K A tile (fp16), warp-per-row ----
        for (int rr = wid; rr < BM; rr += 8) {
            int gr = row0 + rr;
            bool valid = gr < nrows;
            if (MODE == M_PLAIN) {
                const float4* p1 = valid ? (const float4*)(A + (size_t)gr * DIM) : 0;
#pragma unroll
                for (int h = 0; h < 2; h++) {
                    int k4 = lane + 32 * h;
                    if (k4 >= 54) continue;          // 54*4 = 216 = AST
                    float4 v = make_float4(0.f, 0.f, 0.f, 0.f);
                    if (valid && k4 < D4) v = p1[k4];
                    union { uint2 u; __half2 h2[2]; } pk;
                    pk.h2[0] = __floats2half2_rn(v.x, v.y);
                    pk.h2[1] = __floats2half2_rn(v.z, v.w);
                    *reinterpret_cast<uint2*>(&As[rr * AST + k4 * 4]) = pk.u;
                }
            } else if (MODE == M_FUSE && sec < 2) {
                // fp16 row copy: 25 uint4 per row + 2 zero-pad uint4
                const uint4* hrow =
                    (const uint4*)((sec == 0 ? hA : hB2) + (size_t)gr * DIM);
                if (lane < 27) {
                    uint4 v = make_uint4(0, 0, 0, 0);
                    if (valid && lane < 25) v = hrow[lane];
                    *(uint4*)&As[rr * AST + lane * 8] = v;
                }
            } else {
                // QUAL (sec 0) or FUSE sec 2: fp16 x ⊙ fp16 rel, hmul2
                const uint4* px = 0;
                const uint4* pr = 0;
                if (valid) {
                    if (MODE == M_QUAL) {
                        px = (const uint4*)(hX + (size_t)qe[gr] * DIM);
                        pr = (const uint4*)(hR + (size_t)qr[gr] * DIM);
                    } else {
                        px = (const uint4*)(hX + (size_t)gr * DIM);
                        pr = (const uint4*)hR;
                    }
                }
                if (lane < 27) {
                    uint4 o = make_uint4(0, 0, 0, 0);
                    if (valid && lane < 25) {
                        union { uint4 u; __half2 h[4]; } X, R, P;
                        X.u = px[lane];
                        R.u = pr[lane];
                        P.h[0] = __hmul2(X.h[0], R.h[0]);
                        P.h[1] = __hmul2(X.h[1], R.h[1]);
                        P.h[2] = __hmul2(X.h[2], R.h[2]);
                        P.h[3] = __hmul2(X.h[3], R.h[3]);
                        o = P.u;
                    }
                    *(uint4*)&As[rr * AST + lane * 8] = o;
                }
            }
        }
        const __half* Wg = Wh + (size_t)sec * MSZ;
        const uint4* Wg4 = (const uint4*)Wg;

        uint4 w0 = Wg4[tid];
        uint4 w1 = h2nd ? Wg4[s1] : make_uint4(0, 0, 0, 0);
        *(uint4*)&Wb[0][k0a * WST + sg0 * 8] = w0;
        if (h2nd) *(uint4*)&Wb[0][k1a * WST + sg1 * 8] = w1;
        w0 = Wg4[416 + tid];
        if (h2nd) w1 = Wg4[416 + s1];
        __syncthreads();        // As + buf0 visible

        for (int ks = 0; ks < 13; ks++) {
            const __half* wb = Wb[ks & 1];
            uint32_t a0, a1, a2, a3;
            uint32_t aaddr = s2u(&As[(wm * 16 + (lane & 15)) * AST
                                     + ks * 16 + ((lane >> 4) << 3)]);
            asm volatile("ldmatrix.sync.aligned.m8n8.x4.shared.b16 {%0,%1,%2,%3}, [%4];"
                         : "=r"(a0), "=r"(a1), "=r"(a2), "=r"(a3) : "r"(aaddr));
            int brow = ((lane >> 3) & 1) * 8 + (lane & 7);
#pragma unroll
            for (int fp = 0; fp < 6; fp++) {
                int n0 = wn * 104 + fp * 16;
                uint32_t b0, b1, b2, b3;
                uint32_t baddr = s2u(&wb[brow * WST + n0 + ((lane >> 4) << 3)]);
                asm volatile("ldmatrix.sync.aligned.m8n8.x4.trans.shared.b16 "
                             "{%0,%1,%2,%3}, [%4];"
                             : "=r"(b0), "=r"(b1), "=r"(b2), "=r"(b3) : "r"(baddr));
                mma16(acc[2 * fp], a0, a1, a2, a3, b0, b1);
                mma16(acc[2 * fp + 1], a0, a1, a2, a3, b2, b3);
            }
            {
                int n0 = wn * 104 + 96;
                uint32_t b0, b1;
                uint32_t baddr = s2u(&wb[brow * WST + n0]);
                asm volatile("ldmatrix.sync.aligned.m8n8.x2.trans.shared.b16 "
                             "{%0,%1}, [%2];"
                             : "=r"(b0), "=r"(b1) : "r"(baddr));
                mma16(acc[12], a0, a1, a2, a3, b0, b1);
            }
            if (ks < 12) {
                __half* db = Wb[(ks + 1) & 1];
                *(uint4*)&db[k0a * WST + sg0 * 8] = w0;
                if (h2nd) *(uint4*)&db[k1a * WST + sg1 * 8] = w1;
                if (ks < 11) {
                    w0 = Wg4[(size_t)(ks + 2) * 416 + tid];
                    if (h2nd) w1 = Wg4[(size_t)(ks + 2) * 416 + s1];
                }
                __syncthreads();
            }
        }
    }

    // ---- epilogue ----
    int gr0 = row0 + wm * 16 + r4;
    int orow[2];
#pragma unroll
    for (int half = 0; half < 2; half++) {
        int gr = gr0 + 8 * half;
        orow[half] = (gr < nrows) ? ((MODE == M_QUAL) ? opos[gr] : gr) : -1;
    }
#pragma unroll
    for (int f = 0; f < 13; f++) {
        int col = wn * 104 + 8 * f + 2 * kq;
        if (col >= DIM) continue;
#pragma unroll
        for (int half = 0; half < 2; half++) {
            if (orow[half] < 0) continue;
            size_t o = (size_t)orow[half] * DIM + col;
            float v0 = acc[f][2 * half], v1 = acc[f][2 * half + 1];
            if (MODE == M_QUAL) {
                *reinterpret_cast<__half2*>(&hqout[o]) = __floats2half2_rn(v0, v1);
            } else if (MODE == M_FUSE) {
                float t0 = tanhf(v0 * (1.f / 3.f) + bias[col]);
                float t1 = tanhf(v1 * (1.f / 3.f) + bias[col + 1]);
                if (out) { out[o] = t0; out[o + 1] = t1; }
                if (hx2)
                    *reinterpret_cast<__half2*>(&hx2[o]) = __floats2half2_rn(t0, t1);
            } else {
                out[o] = v0; out[o + 1] = v1;
            }
        }
    }
}

// ---------------- CSR gather aggregation (fp16 x + fp16 qproj) ---------------
__global__ void __launch_bounds__(256)
k_agg(const __half* __restrict__ xh, const float* __restrict__ relt,
      const int* __restrict__ e_start, const int* __restrict__ e_cnt,
      const int4* __restrict__ erec, const float* __restrict__ enm,
      const __half* __restrict__ qproj,
      __half* __restrict__ ninh, __half* __restrict__ nouth)
{
    int w = (blockIdx.x * blockDim.x + threadIdx.x) >> 5;
    int lane = threadIdx.x & 31;
    if (w >= 2 * NE) return;
    int d = (w >= NE) ? 1 : 0;
    int n = w - d * NE;

    int c0 = lane;
    int c1 = lane + 32;
    bool has1 = (c1 < D4);

    float4 a0 = make_float4(0.f, 0.f, 0.f, 0.f);
    float4 a1 = a0;

    int beg = e_start[w];
    int end = beg + e_cnt[w];
    if (beg < end) {
        int4 rec = erec[beg];
        float nm = enm[beg];
        for (int idx = beg; idx < end; idx++) {
            int4 rec_n = rec;
            float nm_n = nm;
            if (idx + 1 < end) {
                rec_n = erec[idx + 1];
                nm_n = enm[idx + 1];
            }
            if (nm != 0.f) {
                const uint2* xr = (const uint2*)(xh + (size_t)rec.x * DIM);
                const float4* rr = (const float4*)(relt + (size_t)rec.y * DIM);
                float4 q0 = make_float4(0.f, 0.f, 0.f, 0.f);
                float4 q1 = q0;
                for (int t = rec.z; t < rec.z + rec.w; t++) {
                    const uint2* qp = (const uint2*)(qproj + (size_t)t * DIM);
                    float4 f = h4f(qp[c0]);
                    q0.x += f.x; q0.y += f.y; q0.z += f.z; q0.w += f.w;
                    if (has1) {
                        float4 g = h4f(qp[c1]);
                        q1.x += g.x; q1.y += g.y; q1.z += g.z; q1.w += g.w;
                    }
                }
                float4 xv = h4f(xr[c0]), rv = rr[c0];
                a0.x += nm * xv.x * (ALPHA * rv.x + (1.f - ALPHA) * q0.x);
                a0.y += nm * xv.y * (ALPHA * rv.y + (1.f - ALPHA) * q0.y);
                a0.z += nm * xv.z * (ALPHA * rv.z + (1.f - ALPHA) * q0.z);
                a0.w += nm * xv.w * (ALPHA * rv.w + (1.f - ALPHA) * q0.w);
                if (has1) {
                    float4 xw = h4f(xr[c1]), rw = rr[c1];
                    a1.x += nm * xw.x * (ALPHA * rw.x + (1.f - ALPHA) * q1.x);
                    a1.y += nm * xw.y * (ALPHA * rw.y + (1.f - ALPHA) * q1.y);
                    a1.z += nm * xw.z * (ALPHA * rw.z + (1.f - ALPHA) * q1.z);
                    a1.w += nm * xw.w * (ALPHA * rw.w + (1.f - ALPHA) * q1.w);
                }
            }
            rec = rec_n;
            nm = nm_n;
        }
    }
    __half* ob = (d ? nouth : ninh) + (size_t)n * DIM;
    union { uint2 u; __half2 h2[2]; } s0;
    s0.h2[0] = __floats2half2_rn(a0.x, a0.y);
    s0.h2[1] = __floats2half2_rn(a0.z, a0.w);
    ((uint2*)ob)[c0] = s0.u;
    if (has1) {
        union { uint2 u; __half2 h2[2]; } s1;
        s1.h2[0] = __floats2half2_rn(a1.x, a1.y);
        s1.h2[1] = __floats2half2_rn(a1.z, a1.w);
        ((uint2*)ob)[c1] = s1.u;
    }
}

// ---------------- final batched gathers --------------------------------------
__global__ void k_gather(const float* __restrict__ xf, const float* __restrict__ rf,
                         const int* __restrict__ ent_ix, const int* __restrict__ rel_ix,
                         const int* __restrict__ quals_ix, float* __restrict__ out)
{
    int warp = (blockIdx.x * blockDim.x + threadIdx.x) >> 5;
    int lane = threadIdx.x & 31;
    int nwarp = (gridDim.x * blockDim.x) >> 5;
    const int total = NB * 14;
    for (int r = warp; r < total; r += nwarp) {
        int b = r / 14, s = r - b * 14;
        const float* srcp;
        float* dstp;
        if (s == 0)      { srcp = xf + (size_t)ent_ix[b] * DIM;  dstp = out + OFF_SUB + (size_t)b * DIM; }
        else if (s == 1) { srcp = rf + (size_t)rel_ix[b] * DIM;  dstp = out + OFF_REL + (size_t)b * DIM; }
        else if (s < 8)  { int p = s - 2;
                           srcp = xf + (size_t)quals_ix[b * 2 * QP + 2 * p + 1] * DIM;
                           dstp = out + OFF_QO + ((size_t)b * QP + p) * DIM; }
        else             { int p = s - 8;
                           srcp = rf + (size_t)quals_ix[b * 2 * QP + 2 * p] * DIM;
                           dstp = out + OFF_QR + ((size_t)b * QP + p) * DIM; }
        for (int c = lane; c < D4; c += 32)
            ((float4*)dstp)[c] = ((const float4*)srcp)[c];
    }
}

// ---------------------------------------------------------------------------

extern "C" void kernel_launch(void* const* d_in, const int* in_sizes, int n_in,
                              void* d_out, int out_size)
{
    const float* ent        = (const float*)d_in[0];
    const float* rel0       = (const float*)d_in[1];
    const float* w_in[2]    = {(const float*)d_in[2],  (const float*)d_in[7]};
    const float* w_out[2]   = {(const float*)d_in[3],  (const float*)d_in[8]};
    const float* w_loop[2]  = {(const float*)d_in[4],  (const float*)d_in[9]};
    const float* w_rel[2]   = {(const float*)d_in[5],  (const float*)d_in[10]};
    const float* w_q[2]     = {(const float*)d_in[6],  (const float*)d_in[11]};
    const float* loop_rel[2]= {(const float*)d_in[12], (const float*)d_in[13]};
    const float* bias[2]    = {(const float*)d_in[14], (const float*)d_in[15]};
    const int* ei       = (const int*)d_in[16];
    const int* et       = (const int*)d_in[17];
    const int* qu       = (const int*)d_in[18];
    const int* ent_ix   = (const int*)d_in[19];
    const int* rel_ix   = (const int*)d_in[20];
    const int* quals_ix = (const int*)d_in[21];
    float* out = (float*)d_out;

    float *r1, *dinv, *enm;
    __half *qproj, *ninh, *nouth, *xh, *rh, *lrh, *wh;
    int *ecnt, *estart, *ecur, *qcnt, *qstart, *qcur, *qpos, *part, *psc;
    int4* erec;
    cudaGetSymbolAddress((void**)&qproj,  g_qproj);
    cudaGetSymbolAddress((void**)&ninh,   g_ninh);
    cudaGetSymbolAddress((void**)&nouth,  g_nouth);
    cudaGetSymbolAddress((void**)&xh,     g_xh);
    cudaGetSymbolAddress((void**)&rh,     g_rh);
    cudaGetSymbolAddress((void**)&lrh,    g_lrh);
    cudaGetSymbolAddress((void**)&r1,     g_r1);
    cudaGetSymbolAddress((void**)&dinv,   g_dinv);
    cudaGetSymbolAddress((void**)&enm,    g_enm);
    cudaGetSymbolAddress((void**)&wh,     g_wh);
    cudaGetSymbolAddress((void**)&ecnt,   gi_ecnt);
    cudaGetSymbolAddress((void**)&estart, gi_estart);
    cudaGetSymbolAddress((void**)&ecur,   gi_ecur);
    cudaGetSymbolAddress((void**)&qcnt,   gi_qcnt);
    cudaGetSymbolAddress((void**)&qstart, gi_qstart);
    cudaGetSymbolAddress((void**)&qcur,   gi_qcur);
    cudaGetSymbolAddress((void**)&qpos,   gi_qpos);
    cudaGetSymbolAddress((void**)&erec,   gi_erec);
    cudaGetSymbolAddress((void**)&part,   gi_part);
    cudaGetSymbolAddress((void**)&psc,    gi_psc);

    // ---- fp16 weight conversion (single launch, 10 matrices) ----
    WPtrs wp;
    for (int L = 0; L < 2; L++) {
        wp.p[L * 5 + 0] = w_in[L];
        wp.p[L * 5 + 1] = w_out[L];
        wp.p[L * 5 + 2] = w_loop[L];
        wp.p[L * 5 + 3] = w_q[L];
        wp.p[L * 5 + 4] = w_rel[L];
    }
    k_convW_all<<<(int)((10L * MSZ + 255) / 256), 256>>>(wp, wh);

    // ---- CSR build ----
    k_zero<<<256, 256>>>((float*)ecnt, 2L * NE);
    k_zero<<<512, 256>>>((float*)qcnt, 2L * NEDGE);
    k_counts<<<2048, 256>>>(ei, qu, ecnt, qcnt);

    int nbE = (2 * NE + 1023) / 1024;
    k_scan1<<<nbE, 1024>>>(ecnt, estart, part, 2 * NE);
    k_scan1<<<1, 1024>>>(part, psc, (int*)0, nbE);
    k_scan_add2<<<nbE, 1024>>>(estart, ecur, psc, 2 * NE);

    int nbQ = (2 * NEDGE + 1023) / 1024;
    k_scan1<<<nbQ, 1024>>>(qcnt, qstart, part, 2 * NEDGE);
    k_scan1<<<1, 1024>>>(part, psc, (int*)0, nbQ);
    k_scan_add2<<<nbQ, 1024>>>(qstart, qcur, psc, 2 * NEDGE);

    k_dinv<<<512, 256>>>(ecnt, dinv);
    k_fill_q<<<2048, 256>>>(qu, qcur, qpos);
    k_fill_e<<<2048, 256>>>(ei, et, dinv, qstart, qcnt, ecur, erec, enm);

    // ---- fp16 tables: x (ent), rel, loop_rel (both layers) ----
    k_convH<<<4096, 256>>>(ent, xh, (long)NE * DIM);
    k_convH<<<40, 256>>>(rel0, rh, (long)NR * DIM);
    k_convH<<<1, 64>>>(loop_rel[0], lrh, 200);
    k_convH<<<1, 64>>>(loop_rel[1], lrh + 256, 200);

    float* xf = out + OFF_X;
    float* rf = out + OFF_R;

    for (int L = 0; L < 2; L++) {
        const float* rin = L ? (const float*)r1 : rel0;
        float* rout = L ? rf : r1;

        // qproj[qpos[j]] = fp16((x[q_e[j]] ⊙ rel[q_r[j]]) @ w_q)  -- fp16 fill
        k_gemm<M_QUAL><<<(QROW + BM - 1) / BM, 256>>>(
            0, 0, 0, xh, rh, qu + QROW, qu, qpos,
            wh + (size_t)(L * 5 + 3) * MSZ, 0, qproj, 0, 0, QROW);

        // both-direction record-based CSR gather (fp16 x) -> nin/nout
        k_agg<<<(2 * NE * 32 + 255) / 256, 256>>>(
            xh, rin, estart, ecnt, erec, enm, qproj, ninh, nouth);

        // x_out = tanh(([nin|nout|x⊙loop] @ [w_in;w_out;w_loop])/3 + b)
        // layer 0 -> fp16 xh (in-place safe); layer 1 -> fp32 xf
        k_gemm<M_FUSE><<<(NE + BM - 1) / BM, 256>>>(
            0, ninh, nouth, xh, lrh + (size_t)L * 256, 0, 0, 0,
            wh + (size_t)(L * 5 + 0) * MSZ,
            L ? xf : (float*)0, 0, L ? (__half*)0 : xh, bias[L], NE);

        // r_out = r_in @ w_rel (fp32)
        k_gemm<M_PLAIN><<<(NR + BM - 1) / BM, 256>>>(
            rin, 0, 0, 0, 0, 0, 0, 0,
            wh + (size_t)(L * 5 + 4) * MSZ, rout, 0, 0, 0, NR);

        if (L == 0)     // fp16 rel table for layer 1
            k_convH<<<40, 256>>>(r1, rh, (long)NR * DIM);
    }

    k_gather<<<7168, 256>>>(xf, rf, ent_ix, rel_ix, quals_ix, out);
}